// round 9
// baseline (speedup 1.0000x reference)
#include <cuda_runtime.h>
#include <cuda_fp16.h>
#include <cstdint>

#define Bn 4
#define Tn 2048
#define Cn 1024
#define Hn 16
#define Dn 64

// Inter-kernel tensors in half, [B,H,T,D]
__device__ __half g_Q[Bn * Hn * Tn * Dn];
__device__ __half g_K[Bn * Hn * Tn * Dn];
__device__ __half g_V[Bn * Hn * Tn * Dn];
__device__ __half g_A[Bn * Hn * Tn * Dn];
// Pre-transposed half weights: g_Wt[z][n*Cn + k] = half(W_z[k][n])
__device__ __half g_Wt[4][Cn * Cn];

__device__ __forceinline__ unsigned h2u(float a, float b) {
    __half2 h = __floats2half2_rn(a, b);
    return *(unsigned*)&h;
}
__device__ __forceinline__ void mma_f16(float* c, const unsigned* a, const unsigned* b) {
    asm volatile(
        "mma.sync.aligned.m16n8k16.row.col.f32.f16.f16.f32 "
        "{%0,%1,%2,%3}, {%4,%5,%6,%7}, {%8,%9}, {%0,%1,%2,%3};\n"
        : "+f"(c[0]), "+f"(c[1]), "+f"(c[2]), "+f"(c[3])
        : "r"(a[0]), "r"(a[1]), "r"(a[2]), "r"(a[3]), "r"(b[0]), "r"(b[1]));
}
__device__ __forceinline__ void ldsm_x4(unsigned* r, uint32_t addr) {
    asm volatile(
        "ldmatrix.sync.aligned.m8n8.x4.shared.b16 {%0,%1,%2,%3}, [%4];"
        : "=r"(r[0]), "=r"(r[1]), "=r"(r[2]), "=r"(r[3]) : "r"(addr));
}
__device__ __forceinline__ void ldsm_x4_t(unsigned* r, uint32_t addr) {
    asm volatile(
        "ldmatrix.sync.aligned.m8n8.x4.trans.shared.b16 {%0,%1,%2,%3}, [%4];"
        : "=r"(r[0]), "=r"(r[1]), "=r"(r[2]), "=r"(r[3]) : "r"(addr));
}

// ---------------------------------------------------------------------------
// One-shot weight transpose: g_Wt[z][n][k] = half(W_z[k][n])
// ---------------------------------------------------------------------------
__global__ __launch_bounds__(256) void wtrans_kernel(
    const float* __restrict__ Wq, const float* __restrict__ Wk,
    const float* __restrict__ Wv, const float* __restrict__ Wo)
{
    __shared__ float tile[32][33];
    const int z = blockIdx.z;
    const float* __restrict__ W = (z == 0) ? Wq : (z == 1) ? Wk : (z == 2) ? Wv : Wo;
    const int x0 = blockIdx.x << 5, y0 = blockIdx.y << 5;
    const int tx = threadIdx.x, ty = threadIdx.y;
#pragma unroll
    for (int j = 0; j < 32; j += 8)
        tile[ty + j][tx] = W[(size_t)(y0 + ty + j) * Cn + x0 + tx];
    __syncthreads();
#pragma unroll
    for (int j = 0; j < 32; j += 8)
        g_Wt[z][(size_t)(x0 + ty + j) * Cn + y0 + tx] = __float2half_rn(tile[tx][ty + j]);
}

// ---------------------------------------------------------------------------
// fp16 GEMM core: block 128x128, BK=32, 8 warps (warp 64x32), double-buffered.
// ---------------------------------------------------------------------------
#define QP 40

__global__ __launch_bounds__(256, 2) void qkv_h_kernel(const float* __restrict__ X)
{
    __shared__ __half As[2][128][QP];
    __shared__ __half Bs[2][128][QP];

    const int z = blockIdx.z;
    const __half* __restrict__ Wt = g_Wt[z];
    __half* __restrict__ Y = (z == 0) ? g_Q : (z == 1) ? g_K : g_V;

    const int tid = threadIdx.x;
    const int lane = tid & 31, wid = tid >> 5;
    const int g = lane >> 2, t = lane & 3;
    const int warpm = wid >> 2, warpn = wid & 3;
    const int m0 = blockIdx.y << 7, n0 = blockIdx.x << 7;

    const int row = tid >> 1, e = tid & 1;

    float4 ra[4];
    uint4 rb[2];
    auto ldg = [&](int k0) {
#pragma unroll
        for (int i = 0; i < 4; i++)
            ra[i] = *(const float4*)&X[(size_t)(m0 + row) * Cn + k0 + e * 16 + i * 4];
        const uint4* bp = (const uint4*)&Wt[(size_t)(n0 + row) * Cn + k0 + e * 16];
        rb[0] = bp[0];
        rb[1] = bp[1];
    };
    auto sts = [&](int stg) {
        uint4 u0 = {h2u(ra[0].x, ra[0].y), h2u(ra[0].z, ra[0].w),
                    h2u(ra[1].x, ra[1].y), h2u(ra[1].z, ra[1].w)};
        uint4 u1 = {h2u(ra[2].x, ra[2].y), h2u(ra[2].z, ra[2].w),
                    h2u(ra[3].x, ra[3].y), h2u(ra[3].z, ra[3].w)};
        *(uint4*)&As[stg][row][e * 16] = u0;
        *(uint4*)&As[stg][row][e * 16 + 8] = u1;
        *(uint4*)&Bs[stg][row][e * 16] = rb[0];
        *(uint4*)&Bs[stg][row][e * 16 + 8] = rb[1];
    };

    float c[4][4][4] = {};

    ldg(0);
    sts(0);
    ldg(32);
    __syncthreads();

    const unsigned a_lr = (lane & 7) + (((lane >> 3) & 1) << 3);
    const unsigned a_lc = ((lane >> 4) & 1) << 3;
    const unsigned b_lr = (((lane >> 4) & 1) << 3) + (lane & 7);
    const unsigned b_lc = ((lane >> 3) & 1) << 3;
    const uint32_t aBase = (uint32_t)__cvta_generic_to_shared(&As[0][0][0]);
    const uint32_t bBase = (uint32_t)__cvta_generic_to_shared(&Bs[0][0][0]);

    for (int it = 0; it < Cn / 32; ++it) {
        const int cur = it & 1;
        if (it + 1 < Cn / 32) sts(cur ^ 1);
        if (it + 2 < Cn / 32) ldg((it + 2) << 5);

#pragma unroll
        for (int ks = 0; ks < 2; ks++) {
            const int kk = ks << 4;
            unsigned bf[2][4];
#pragma unroll
            for (int p = 0; p < 2; p++) {
                const unsigned rn = warpn * 32 + p * 16 + b_lr;
                ldsm_x4(bf[p], bBase + 2u * (cur * 128 * QP + rn * QP + kk + b_lc));
            }
#pragma unroll
            for (int mi = 0; mi < 4; mi++) {
                unsigned a[4];
                const unsigned rm = warpm * 64 + mi * 16 + a_lr;
                ldsm_x4(a, aBase + 2u * (cur * 128 * QP + rm * QP + kk + a_lc));
#pragma unroll
                for (int nj = 0; nj < 4; nj++) {
                    unsigned bb[2] = {bf[nj >> 1][(nj & 1) * 2],
                                      bf[nj >> 1][(nj & 1) * 2 + 1]};
                    mma_f16(c[mi][nj], a, bb);
                }
            }
        }
        __syncthreads();
    }

#pragma unroll
    for (int mi = 0; mi < 4; mi++) {
#pragma unroll
        for (int r = 0; r < 2; r++) {
            const int mrow = m0 + warpm * 64 + mi * 16 + g + 8 * r;
            const int b_ = mrow >> 11, t_ = mrow & (Tn - 1);
#pragma unroll
            for (int nj = 0; nj < 4; nj++) {
                const int n = n0 + warpn * 32 + nj * 8 + 2 * t;
                const int h = n >> 6, d = n & 63;
                __half2 hv = __floats2half2_rn(c[mi][nj][2 * r], c[mi][nj][2 * r + 1]);
                *(__half2*)&Y[(size_t)((b_ * Hn + h) * Tn + t_) * Dn + d] = hv;
            }
        }
    }
}

// ---------------------------------------------------------------------------
// oproj: out = A @ Wo + bo (fp32 out). A gathered from g_A (half).
// ---------------------------------------------------------------------------
__global__ __launch_bounds__(256, 2) void oproj_h_kernel(
    const float* __restrict__ bo, float* __restrict__ out)
{
    __shared__ __half As[2][128][QP];
    __shared__ __half Bs[2][128][QP];
    const __half* __restrict__ Wt = g_Wt[3];

    const int tid = threadIdx.x;
    const int lane = tid & 31, wid = tid >> 5;
    const int g = lane >> 2, t = lane & 3;
    const int warpm = wid >> 2, warpn = wid & 3;
    const int m0 = blockIdx.y << 7, n0 = blockIdx.x << 7;

    const int row = tid >> 1, e = tid & 1;
    const int m = m0 + row;
    const int mb = m >> 11, mt = m & (Tn - 1);

    uint4 ra[2], rb[2];
    auto ldg = [&](int k0) {
        const int hh = k0 >> 6, dd = (k0 & 63) + e * 16;
        const uint4* ap = (const uint4*)&g_A[(size_t)((mb * Hn + hh) * Tn + mt) * Dn + dd];
        ra[0] = ap[0];
        ra[1] = ap[1];
        const uint4* bp = (const uint4*)&Wt[(size_t)(n0 + row) * Cn + k0 + e * 16];
        rb[0] = bp[0];
        rb[1] = bp[1];
    };
    auto sts = [&](int stg) {
        *(uint4*)&As[stg][row][e * 16] = ra[0];
        *(uint4*)&As[stg][row][e * 16 + 8] = ra[1];
        *(uint4*)&Bs[stg][row][e * 16] = rb[0];
        *(uint4*)&Bs[stg][row][e * 16 + 8] = rb[1];
    };

    float c[4][4][4] = {};

    ldg(0);
    sts(0);
    ldg(32);
    __syncthreads();

    const unsigned a_lr = (lane & 7) + (((lane >> 3) & 1) << 3);
    const unsigned a_lc = ((lane >> 4) & 1) << 3;
    const unsigned b_lr = (((lane >> 4) & 1) << 3) + (lane & 7);
    const unsigned b_lc = ((lane >> 3) & 1) << 3;
    const uint32_t aBase = (uint32_t)__cvta_generic_to_shared(&As[0][0][0]);
    const uint32_t bBase = (uint32_t)__cvta_generic_to_shared(&Bs[0][0][0]);

    for (int it = 0; it < Cn / 32; ++it) {
        const int cur = it & 1;
        if (it + 1 < Cn / 32) sts(cur ^ 1);
        if (it + 2 < Cn / 32) ldg((it + 2) << 5);

#pragma unroll
        for (int ks = 0; ks < 2; ks++) {
            const int kk = ks << 4;
            unsigned bf[2][4];
#pragma unroll
            for (int p = 0; p < 2; p++) {
                const unsigned rn = warpn * 32 + p * 16 + b_lr;
                ldsm_x4(bf[p], bBase + 2u * (cur * 128 * QP + rn * QP + kk + b_lc));
            }
#pragma unroll
            for (int mi = 0; mi < 4; mi++) {
                unsigned a[4];
                const unsigned rm = warpm * 64 + mi * 16 + a_lr;
                ldsm_x4(a, aBase + 2u * (cur * 128 * QP + rm * QP + kk + a_lc));
#pragma unroll
                for (int nj = 0; nj < 4; nj++) {
                    unsigned bb[2] = {bf[nj >> 1][(nj & 1) * 2],
                                      bf[nj >> 1][(nj & 1) * 2 + 1]};
                    mma_f16(c[mi][nj], a, bb);
                }
            }
        }
        __syncthreads();
    }

#pragma unroll
    for (int mi = 0; mi < 4; mi++) {
#pragma unroll
        for (int r = 0; r < 2; r++) {
            const int mrow = m0 + warpm * 64 + mi * 16 + g + 8 * r;
#pragma unroll
            for (int nj = 0; nj < 4; nj++) {
                const int n = n0 + warpn * 32 + nj * 8 + 2 * t;
                float2 bias = *(const float2*)&bo[n];
                float2 v = {c[mi][nj][2 * r] + bias.x, c[mi][nj][2 * r + 1] + bias.y};
                *(float2*)&out[(size_t)mrow * Cn + n] = v;
            }
        }
    }
}

// ---------------------------------------------------------------------------
// Flash attention fp16: 8 warps, 128 q-rows/block, kv tiles of 64.
//   Ks [key][d]  half pitch 72 — LDSM (B for S)
//   Vs [key][d]  half pitch 72 — LDSM.trans (B for PV)
//   Ps [q][key]  half pitch 72 (128 rows) — LDSM (A for PV); also Q staging
// ---------------------------------------------------------------------------
#define FP 72

__global__ __launch_bounds__(256) void flash_h_kernel()
{
    __shared__ __half Ks[64][FP];
    __shared__ __half Vs[64][FP];
    __shared__ __half Ps[128][FP];

    const int qb = blockIdx.x;
    const int h = blockIdx.y, b = blockIdx.z;
    const int tid = threadIdx.x;
    const int lane = tid & 31, wid = tid >> 5;
    const int g = lane >> 2, t = lane & 3;
    const int q0 = qb << 7;
    const int qrow = (wid << 4) + g;        // warp-owned rows qrow, qrow+8 (0..127)

    const size_t base = (size_t)((b * Hn + h) * Tn) * Dn;
    const __half* __restrict__ Qg = g_Q + base;
    const __half* __restrict__ Kg = g_K + base;
    const __half* __restrict__ Vg = g_V + base;

    // ---- stage Q (128 x 64 halves) into Ps: 2 threads/row, 4 uint4 each ----
    const int srow = tid >> 1, se = tid & 1;
    {
        const uint4* qp = (const uint4*)&Qg[(size_t)(q0 + srow) * Dn + se * 32];
#pragma unroll
        for (int j = 0; j < 4; j++)
            *(uint4*)&Ps[srow][se * 32 + j * 8] = qp[j];
    }
    __syncthreads();

    const unsigned a_lr = (lane & 7) + (((lane >> 3) & 1) << 3);
    const unsigned a_lc = ((lane >> 4) & 1) << 3;
    const uint32_t ksBase = (uint32_t)__cvta_generic_to_shared(&Ks[0][0]);
    const uint32_t vsBase = (uint32_t)__cvta_generic_to_shared(&Vs[0][0]);
    const uint32_t psBase = (uint32_t)__cvta_generic_to_shared(&Ps[0][0]);

    unsigned qa[4][4];
#pragma unroll
    for (int ks = 0; ks < 4; ks++)
        ldsm_x4(qa[ks], psBase + 2u * ((wid * 16 + a_lr) * FP + ks * 16 + a_lc));
    __syncthreads();

    // K/V staging split: tids 0-127 stage K, 128-255 stage V (2 threads/row)
    const int kvrow = (tid & 127) >> 1;
    const int kse = tid & 1;
    const bool doV = (tid >= 128);

    float o[8][4] = {};
    float mv0 = -1e30f, mv1 = -1e30f, l0 = 0.0f, l1 = 0.0f;
    const int nkv = (qb << 1) + 2;
    const int r0g = q0 + qrow, r1g = r0g + 8;

    for (int kb = 0; kb < nkv; kb++) {
        const int k0 = kb << 6;
        {
            const __half* src = doV ? Vg : Kg;
            const uint4* p = (const uint4*)&src[(size_t)(k0 + kvrow) * Dn + kse * 32];
            __half* dst = doV ? &Vs[kvrow][kse * 32] : &Ks[kvrow][kse * 32];
#pragma unroll
            for (int j = 0; j < 4; j++)
                *(uint4*)&dst[j * 8] = p[j];
        }
        __syncthreads();

        // ---- S = Q @ K^T ----
        float s[8][4] = {};
#pragma unroll
        for (int nj = 0; nj < 8; nj++) {
            unsigned bf[8];
            const uint32_t ad = ksBase + 2u * ((nj * 8 + (lane & 7)) * FP + (lane >> 3) * 8);
            ldsm_x4(bf, ad);
            ldsm_x4(bf + 4, ad + 64);
#pragma unroll
            for (int ks = 0; ks < 4; ks++) {
                unsigned bb[2] = {bf[2 * ks], bf[2 * ks + 1]};
                mma_f16(s[nj], qa[ks], bb);
            }
        }

        // ---- scale + causal mask (global-index compare) ----
        const bool msk = (k0 + 63 > q0);
#pragma unroll
        for (int nj = 0; nj < 8; nj++) {
#pragma unroll
            for (int e2 = 0; e2 < 4; e2++) s[nj][e2] *= 0.125f;
            if (msk) {
                const int col0 = k0 + nj * 8 + 2 * t, col1 = col0 + 1;
                if (col0 > r0g) s[nj][0] = -1e30f;
                if (col1 > r0g) s[nj][1] = -1e30f;
                if (col0 > r1g) s[nj][2] = -1e30f;
                if (col1 > r1g) s[nj][3] = -1e30f;
            }
        }

        // ---- online softmax (quad shuffles; warp owns its rows) ----
        float mt0 = -1e30f, mt1 = -1e30f;
#pragma unroll
        for (int nj = 0; nj < 8; nj++) {
            mt0 = fmaxf(mt0, fmaxf(s[nj][0], s[nj][1]));
            mt1 = fmaxf(mt1, fmaxf(s[nj][2], s[nj][3]));
        }
        mt0 = fmaxf(mt0, __shfl_xor_sync(0xffffffffu, mt0, 1));
        mt0 = fmaxf(mt0, __shfl_xor_sync(0xffffffffu, mt0, 2));
        mt1 = fmaxf(mt1, __shfl_xor_sync(0xffffffffu, mt1, 1));
        mt1 = fmaxf(mt1, __shfl_xor_sync(0xffffffffu, mt1, 2));

        const float mn0 = fmaxf(mv0, mt0);
        const float mn1 = fmaxf(mv1, mt1);
        float sum0 = 0.0f, sum1 = 0.0f;
#pragma unroll
        for (int nj = 0; nj < 8; nj++) {
            float p0 = __expf(s[nj][0] - mn0);
            float p1 = __expf(s[nj][1] - mn0);
            float p2 = __expf(s[nj][2] - mn1);
            float p3 = __expf(s[nj][3] - mn1);
            sum0 += p0 + p1;
            sum1 += p2 + p3;
            *(__half2*)&Ps[qrow][nj * 8 + 2 * t] = __floats2half2_rn(p0, p1);
            *(__half2*)&Ps[qrow + 8][nj * 8 + 2 * t] = __floats2half2_rn(p2, p3);
        }
        sum0 += __shfl_xor_sync(0xffffffffu, sum0, 1);
        sum0 += __shfl_xor_sync(0xffffffffu, sum0, 2);
        sum1 += __shfl_xor_sync(0xffffffffu, sum1, 1);
        sum1 += __shfl_xor_sync(0xffffffffu, sum1, 2);

        const float cf0 = __expf(mv0 - mn0);
        const float cf1 = __expf(mv1 - mn1);
        l0 = l0 * cf0 + sum0;
        l1 = l1 * cf1 + sum1;
        mv0 = mn0;
        mv1 = mn1;
#pragma unroll
        for (int nj = 0; nj < 8; nj++) {
            o[nj][0] *= cf0; o[nj][1] *= cf0;
            o[nj][2] *= cf1; o[nj][3] *= cf1;
        }
        __syncwarp();

        // ---- O += P @ V ----
        unsigned pa[4][4];
#pragma unroll
        for (int ks = 0; ks < 4; ks++)
            ldsm_x4(pa[ks], psBase + 2u * ((wid * 16 + a_lr) * FP + ks * 16 + a_lc));
#pragma unroll
        for (int nj = 0; nj < 8; nj++) {
            unsigned vf[8];
            ldsm_x4_t(vf, vsBase + 2u * (lane * FP + nj * 8));
            ldsm_x4_t(vf + 4, vsBase + 2u * ((32 + lane) * FP + nj * 8));
#pragma unroll
            for (int ks = 0; ks < 4; ks++) {
                unsigned bb[2] = {vf[2 * ks], vf[2 * ks + 1]};
                mma_f16(o[nj], pa[ks], bb);
            }
        }
        __syncthreads();
    }

    // ---- normalize + write g_A (half) ----
    __half* __restrict__ Ag = g_A + base;
    const float inv0 = 1.0f / l0, inv1 = 1.0f / l1;
#pragma unroll
    for (int nj = 0; nj < 8; nj++) {
        const int d = nj * 8 + 2 * t;
        *(__half2*)&Ag[(size_t)(q0 + qrow) * Dn + d] =
            __floats2half2_rn(o[nj][0] * inv0, o[nj][1] * inv0);
        *(__half2*)&Ag[(size_t)(q0 + qrow + 8) * Dn + d] =
            __floats2half2_rn(o[nj][2] * inv1, o[nj][3] * inv1);
    }
}

// ---------------------------------------------------------------------------
extern "C" void kernel_launch(void* const* d_in, const int* in_sizes, int n_in,
                              void* d_out, int out_size)
{
    const float* x  = (const float*)d_in[0];
    const float* Wq = (const float*)d_in[1];
    const float* Wk = (const float*)d_in[2];
    const float* Wv = (const float*)d_in[3];
    const float* Wo = (const float*)d_in[4];
    const float* bo = (const float*)d_in[5];
    float* out = (float*)d_out;

    wtrans_kernel<<<dim3(Cn / 32, Cn / 32, 4), dim3(32, 8)>>>(Wq, Wk, Wv, Wo);

    qkv_h_kernel<<<dim3(Cn / 128, (Bn * Tn) / 128, 3), 256>>>(x);

    flash_h_kernel<<<dim3(Tn / 128, Hn, Bn), 256>>>();

    oproj_h_kernel<<<dim3(Cn / 128, (Bn * Tn) / 128), 256>>>(bo, out);
}

// round 10
// speedup vs baseline: 1.2227x; 1.2227x over previous
#include <cuda_runtime.h>
#include <cuda_fp16.h>
#include <cstdint>

#define Bn 4
#define Tn 2048
#define Cn 1024
#define Hn 16
#define Dn 64

// Inter-kernel tensors in half, [B,H,T,D]
__device__ __half g_Q[Bn * Hn * Tn * Dn];
__device__ __half g_K[Bn * Hn * Tn * Dn];
__device__ __half g_V[Bn * Hn * Tn * Dn];
__device__ __half g_A[Bn * Hn * Tn * Dn];
__device__ __half g_Xh[Bn * Tn * Cn];         // half(x), row-major [B*T][C]
__device__ __half g_Wt[4][Cn * Cn];           // Wt[z][n][k] = half(W_z[k][n])

__device__ __forceinline__ void mma_f16(float* c, const unsigned* a, const unsigned* b) {
    asm volatile(
        "mma.sync.aligned.m16n8k16.row.col.f32.f16.f16.f32 "
        "{%0,%1,%2,%3}, {%4,%5,%6,%7}, {%8,%9}, {%0,%1,%2,%3};\n"
        : "+f"(c[0]), "+f"(c[1]), "+f"(c[2]), "+f"(c[3])
        : "r"(a[0]), "r"(a[1]), "r"(a[2]), "r"(a[3]), "r"(b[0]), "r"(b[1]));
}
__device__ __forceinline__ void ldsm_x4(unsigned* r, uint32_t addr) {
    asm volatile(
        "ldmatrix.sync.aligned.m8n8.x4.shared.b16 {%0,%1,%2,%3}, [%4];"
        : "=r"(r[0]), "=r"(r[1]), "=r"(r[2]), "=r"(r[3]) : "r"(addr));
}
__device__ __forceinline__ void ldsm_x4_t(unsigned* r, uint32_t addr) {
    asm volatile(
        "ldmatrix.sync.aligned.m8n8.x4.trans.shared.b16 {%0,%1,%2,%3}, [%4];"
        : "=r"(r[0]), "=r"(r[1]), "=r"(r[2]), "=r"(r[3]) : "r"(addr));
}
__device__ __forceinline__ void cp16(uint32_t dst, const void* src) {
    asm volatile("cp.async.cg.shared.global [%0], [%1], 16;" :: "r"(dst), "l"(src) : "memory");
}

// ---------------------------------------------------------------------------
// One-shot input conversion: g_Xh = half(x)
// ---------------------------------------------------------------------------
__global__ __launch_bounds__(256) void xconv_kernel(const float* __restrict__ X)
{
    const int i = (blockIdx.x * 256 + threadIdx.x) * 4;
    float4 v = *(const float4*)&X[i];
    __half2 h0 = __floats2half2_rn(v.x, v.y);
    __half2 h1 = __floats2half2_rn(v.z, v.w);
    *(uint2*)&g_Xh[i] = make_uint2(*(unsigned*)&h0, *(unsigned*)&h1);
}

// ---------------------------------------------------------------------------
// One-shot weight transpose: g_Wt[z][n][k] = half(W_z[k][n])
// ---------------------------------------------------------------------------
__global__ __launch_bounds__(256) void wtrans_kernel(
    const float* __restrict__ Wq, const float* __restrict__ Wk,
    const float* __restrict__ Wv, const float* __restrict__ Wo)
{
    __shared__ float tile[32][33];
    const int z = blockIdx.z;
    const float* __restrict__ W = (z == 0) ? Wq : (z == 1) ? Wk : (z == 2) ? Wv : Wo;
    const int x0 = blockIdx.x << 5, y0 = blockIdx.y << 5;
    const int tx = threadIdx.x, ty = threadIdx.y;
#pragma unroll
    for (int j = 0; j < 32; j += 8)
        tile[ty + j][tx] = W[(size_t)(y0 + ty + j) * Cn + x0 + tx];
    __syncthreads();
#pragma unroll
    for (int j = 0; j < 32; j += 8)
        g_Wt[z][(size_t)(x0 + ty + j) * Cn + y0 + tx] = __float2half_rn(tile[tx][ty + j]);
}

// ---------------------------------------------------------------------------
// fp16 GEMM: block 128x128, BK=32, 8 warps (warp 64x32), 3-stage cp.async.
// As/Bs: [stage][row][k] half, pitch QP=40.
// ---------------------------------------------------------------------------
#define QP 40
#define NST 3
#define STG_H (128 * QP)                 // halves per stage per array
#define GEMM_SMEM (2 * NST * STG_H * 2)  // bytes

// compute one BK=32 block from stage `cur`; shared by qkv/oproj
#define GEMM_COMPUTE()                                                          \
    do {                                                                        \
        const uint32_t so = 2u * (unsigned)(cur * STG_H);                       \
        _Pragma("unroll")                                                       \
        for (int ks = 0; ks < 2; ks++) {                                        \
            const int kk = ks << 4;                                             \
            unsigned bf[2][4];                                                  \
            _Pragma("unroll")                                                   \
            for (int p = 0; p < 2; p++) {                                       \
                const unsigned rn = warpn * 32 + p * 16 + b_lr;                 \
                ldsm_x4(bf[p], bBase + so + 2u * (rn * QP + kk + b_lc));        \
            }                                                                   \
            _Pragma("unroll")                                                   \
            for (int mi = 0; mi < 4; mi++) {                                    \
                unsigned a[4];                                                  \
                const unsigned rm = warpm * 64 + mi * 16 + a_lr;                \
                ldsm_x4(a, aBase + so + 2u * (rm * QP + kk + a_lc));            \
                _Pragma("unroll")                                               \
                for (int nj = 0; nj < 4; nj++) {                                \
                    unsigned bb[2] = {bf[nj >> 1][(nj & 1) * 2],                \
                                      bf[nj >> 1][(nj & 1) * 2 + 1]};           \
                    mma_f16(c[mi][nj], a, bb);                                  \
                }                                                               \
            }                                                                   \
        }                                                                       \
    } while (0)

__global__ __launch_bounds__(256, 2) void qkv_h_kernel()
{
    extern __shared__ __align__(16) __half smg[];
    __half* As = smg;
    __half* Bs = smg + NST * STG_H;

    const int z = blockIdx.z;
    const __half* __restrict__ Wt = g_Wt[z];
    __half* __restrict__ Y = (z == 0) ? g_Q : (z == 1) ? g_K : g_V;

    const int tid = threadIdx.x;
    const int lane = tid & 31, wid = tid >> 5;
    const int g = lane >> 2, t = lane & 3;
    const int warpm = wid >> 2, warpn = wid & 3;
    const int m0 = blockIdx.y << 7, n0 = blockIdx.x << 7;

    const int row = tid >> 1, e = tid & 1;
    const __half* Asrc = &g_Xh[(size_t)(m0 + row) * Cn + e * 16];
    const __half* Bsrc = &Wt[(size_t)(n0 + row) * Cn + e * 16];
    const uint32_t aSm = (uint32_t)__cvta_generic_to_shared(&As[row * QP + e * 16]);
    const uint32_t bSm = (uint32_t)__cvta_generic_to_shared(&Bs[row * QP + e * 16]);

    auto stage = [&](int stg, int k0) {
        const uint32_t ao = aSm + 2u * (unsigned)(stg * STG_H);
        cp16(ao, Asrc + k0);
        cp16(ao + 16, Asrc + k0 + 8);
        const uint32_t bo2 = bSm + 2u * (unsigned)(stg * STG_H);
        cp16(bo2, Bsrc + k0);
        cp16(bo2 + 16, Bsrc + k0 + 8);
        asm volatile("cp.async.commit_group;" ::: "memory");
    };

    float c[4][4][4] = {};
    stage(0, 0);
    stage(1, 32);

    const unsigned a_lr = (lane & 7) + (((lane >> 3) & 1) << 3);
    const unsigned a_lc = ((lane >> 4) & 1) << 3;
    const unsigned b_lr = (((lane >> 4) & 1) << 3) + (lane & 7);
    const unsigned b_lc = ((lane >> 3) & 1) << 3;
    const uint32_t aBase = (uint32_t)__cvta_generic_to_shared(As);
    const uint32_t bBase = (uint32_t)__cvta_generic_to_shared(Bs);

    for (int it = 0; it < Cn / 32; ++it) {
        const int cur = it % NST;
        if (it + 2 < Cn / 32)
            asm volatile("cp.async.wait_group 1;" ::: "memory");
        else
            asm volatile("cp.async.wait_group 0;" ::: "memory");
        __syncthreads();
        GEMM_COMPUTE();
        if (it + 2 < Cn / 32) stage((it + 2) % NST, (it + 2) * 32);
        __syncthreads();
    }

#pragma unroll
    for (int mi = 0; mi < 4; mi++) {
#pragma unroll
        for (int r = 0; r < 2; r++) {
            const int mrow = m0 + warpm * 64 + mi * 16 + g + 8 * r;
            const int b_ = mrow >> 11, t_ = mrow & (Tn - 1);
#pragma unroll
            for (int nj = 0; nj < 4; nj++) {
                const int n = n0 + warpn * 32 + nj * 8 + 2 * t;
                const int h = n >> 6, d = n & 63;
                __half2 hv = __floats2half2_rn(c[mi][nj][2 * r], c[mi][nj][2 * r + 1]);
                *(__half2*)&Y[(size_t)((b_ * Hn + h) * Tn + t_) * Dn + d] = hv;
            }
        }
    }
}

__global__ __launch_bounds__(256, 2) void oproj_h_kernel(
    const float* __restrict__ bo, float* __restrict__ out)
{
    extern __shared__ __align__(16) __half smg[];
    __half* As = smg;
    __half* Bs = smg + NST * STG_H;
    const __half* __restrict__ Wt = g_Wt[3];

    const int tid = threadIdx.x;
    const int lane = tid & 31, wid = tid >> 5;
    const int g = lane >> 2, t = lane & 3;
    const int warpm = wid >> 2, warpn = wid & 3;
    const int m0 = blockIdx.y << 7, n0 = blockIdx.x << 7;

    const int row = tid >> 1, e = tid & 1;
    const int m = m0 + row;
    const int mb = m >> 11, mt = m & (Tn - 1);
    const __half* aRowBase = &g_A[((size_t)(mb * Hn) * Tn + mt) * Dn + e * 16];
    const __half* Bsrc = &Wt[(size_t)(n0 + row) * Cn + e * 16];
    const uint32_t aSm = (uint32_t)__cvta_generic_to_shared(&As[row * QP + e * 16]);
    const uint32_t bSm = (uint32_t)__cvta_generic_to_shared(&Bs[row * QP + e * 16]);

    auto stage = [&](int stg, int k0) {
        const __half* as = aRowBase + (size_t)(k0 >> 6) * Tn * Dn + (k0 & 63);
        const uint32_t ao = aSm + 2u * (unsigned)(stg * STG_H);
        cp16(ao, as);
        cp16(ao + 16, as + 8);
        const uint32_t bo2 = bSm + 2u * (unsigned)(stg * STG_H);
        cp16(bo2, Bsrc + k0);
        cp16(bo2 + 16, Bsrc + k0 + 8);
        asm volatile("cp.async.commit_group;" ::: "memory");
    };

    float c[4][4][4] = {};
    stage(0, 0);
    stage(1, 32);

    const unsigned a_lr = (lane & 7) + (((lane >> 3) & 1) << 3);
    const unsigned a_lc = ((lane >> 4) & 1) << 3;
    const unsigned b_lr = (((lane >> 4) & 1) << 3) + (lane & 7);
    const unsigned b_lc = ((lane >> 3) & 1) << 3;
    const uint32_t aBase = (uint32_t)__cvta_generic_to_shared(As);
    const uint32_t bBase = (uint32_t)__cvta_generic_to_shared(Bs);

    for (int it = 0; it < Cn / 32; ++it) {
        const int cur = it % NST;
        if (it + 2 < Cn / 32)
            asm volatile("cp.async.wait_group 1;" ::: "memory");
        else
            asm volatile("cp.async.wait_group 0;" ::: "memory");
        __syncthreads();
        GEMM_COMPUTE();
        if (it + 2 < Cn / 32) stage((it + 2) % NST, (it + 2) * 32);
        __syncthreads();
    }

#pragma unroll
    for (int mi = 0; mi < 4; mi++) {
#pragma unroll
        for (int r = 0; r < 2; r++) {
            const int mrow = m0 + warpm * 64 + mi * 16 + g + 8 * r;
#pragma unroll
            for (int nj = 0; nj < 4; nj++) {
                const int n = n0 + warpn * 32 + nj * 8 + 2 * t;
                float2 bias = *(const float2*)&bo[n];
                float2 v = {c[mi][nj][2 * r] + bias.x, c[mi][nj][2 * r + 1] + bias.y};
                *(float2*)&out[(size_t)mrow * Cn + n] = v;
            }
        }
    }
}

// ---------------------------------------------------------------------------
// Flash attention fp16 (identical to Round-8 passing version): Br=Bc=64,
// 4 warps, Q frags in registers.
// ---------------------------------------------------------------------------
#define FP 72

__global__ __launch_bounds__(128) void flash_h_kernel()
{
    __shared__ __half Ks[64][FP];
    __shared__ __half Vs[64][FP];
    __shared__ __half Ps[64][FP];

    const int qb = blockIdx.x;
    const int h = blockIdx.y, b = blockIdx.z;
    const int tid = threadIdx.x;
    const int lane = tid & 31, wid = tid >> 5;
    const int g = lane >> 2, t = lane & 3;
    const int q0 = qb << 6;
    const int qrow = (wid << 4) + g;

    const size_t base = (size_t)((b * Hn + h) * Tn) * Dn;
    const __half* __restrict__ Qg = g_Q + base;
    const __half* __restrict__ Kg = g_K + base;
    const __half* __restrict__ Vg = g_V + base;

    const int srow = tid >> 1, se = tid & 1;

    {
        const uint4* qp = (const uint4*)&Qg[(size_t)(q0 + srow) * Dn + se * 32];
#pragma unroll
        for (int j = 0; j < 4; j++)
            *(uint4*)&Ps[srow][se * 32 + j * 8] = qp[j];
    }
    __syncthreads();

    const unsigned a_lr = (lane & 7) + (((lane >> 3) & 1) << 3);
    const unsigned a_lc = ((lane >> 4) & 1) << 3;
    const uint32_t ksBase = (uint32_t)__cvta_generic_to_shared(&Ks[0][0]);
    const uint32_t vsBase = (uint32_t)__cvta_generic_to_shared(&Vs[0][0]);
    const uint32_t psBase = (uint32_t)__cvta_generic_to_shared(&Ps[0][0]);

    unsigned qa[4][4];
#pragma unroll
    for (int ks = 0; ks < 4; ks++)
        ldsm_x4(qa[ks], psBase + 2u * ((wid * 16 + a_lr) * FP + ks * 16 + a_lc));
    __syncthreads();

    float o[8][4] = {};
    float mv0 = -1e30f, mv1 = -1e30f, l0 = 0.0f, l1 = 0.0f;

    for (int kb = 0; kb <= qb; kb++) {
        const int k0 = kb << 6;
        {
            const uint4* kp = (const uint4*)&Kg[(size_t)(k0 + srow) * Dn + se * 32];
            const uint4* vp = (const uint4*)&Vg[(size_t)(k0 + srow) * Dn + se * 32];
#pragma unroll
            for (int j = 0; j < 4; j++) {
                *(uint4*)&Ks[srow][se * 32 + j * 8] = kp[j];
                *(uint4*)&Vs[srow][se * 32 + j * 8] = vp[j];
            }
        }
        __syncthreads();

        float s[8][4] = {};
#pragma unroll
        for (int nj = 0; nj < 8; nj++) {
            unsigned bf[8];
            const uint32_t ad = ksBase + 2u * ((nj * 8 + (lane & 7)) * FP + (lane >> 3) * 8);
            ldsm_x4(bf, ad);
            ldsm_x4(bf + 4, ad + 64);
#pragma unroll
            for (int ks = 0; ks < 4; ks++) {
                unsigned bb[2] = {bf[2 * ks], bf[2 * ks + 1]};
                mma_f16(s[nj], qa[ks], bb);
            }
        }

        const bool diag = (kb == qb);
#pragma unroll
        for (int nj = 0; nj < 8; nj++) {
#pragma unroll
            for (int e2 = 0; e2 < 4; e2++) s[nj][e2] *= 0.125f;
            if (diag) {
                const int col0 = nj * 8 + 2 * t, col1 = col0 + 1;
                if (col0 > qrow) s[nj][0] = -1e30f;
                if (col1 > qrow) s[nj][1] = -1e30f;
                if (col0 > qrow + 8) s[nj][2] = -1e30f;
                if (col1 > qrow + 8) s[nj][3] = -1e30f;
            }
        }

        float mt0 = -1e30f, mt1 = -1e30f;
#pragma unroll
        for (int nj = 0; nj < 8; nj++) {
            mt0 = fmaxf(mt0, fmaxf(s[nj][0], s[nj][1]));
            mt1 = fmaxf(mt1, fmaxf(s[nj][2], s[nj][3]));
        }
        mt0 = fmaxf(mt0, __shfl_xor_sync(0xffffffffu, mt0, 1));
        mt0 = fmaxf(mt0, __shfl_xor_sync(0xffffffffu, mt0, 2));
        mt1 = fmaxf(mt1, __shfl_xor_sync(0xffffffffu, mt1, 1));
        mt1 = fmaxf(mt1, __shfl_xor_sync(0xffffffffu, mt1, 2));

        const float mn0 = fmaxf(mv0, mt0);
        const float mn1 = fmaxf(mv1, mt1);
        float sum0 = 0.0f, sum1 = 0.0f;
#pragma unroll
        for (int nj = 0; nj < 8; nj++) {
            float p0 = __expf(s[nj][0] - mn0);
            float p1 = __expf(s[nj][1] - mn0);
            float p2 = __expf(s[nj][2] - mn1);
            float p3 = __expf(s[nj][3] - mn1);
            sum0 += p0 + p1;
            sum1 += p2 + p3;
            *(__half2*)&Ps[qrow][nj * 8 + 2 * t] = __floats2half2_rn(p0, p1);
            *(__half2*)&Ps[qrow + 8][nj * 8 + 2 * t] = __floats2half2_rn(p2, p3);
        }
        sum0 += __shfl_xor_sync(0xffffffffu, sum0, 1);
        sum0 += __shfl_xor_sync(0xffffffffu, sum0, 2);
        sum1 += __shfl_xor_sync(0xffffffffu, sum1, 1);
        sum1 += __shfl_xor_sync(0xffffffffu, sum1, 2);

        const float cf0 = __expf(mv0 - mn0);
        const float cf1 = __expf(mv1 - mn1);
        l0 = l0 * cf0 + sum0;
        l1 = l1 * cf1 + sum1;
        mv0 = mn0;
        mv1 = mn1;
#pragma unroll
        for (int nj = 0; nj < 8; nj++) {
            o[nj][0] *= cf0; o[nj][1] *= cf0;
            o[nj][2] *= cf1; o[nj][3] *= cf1;
        }
        __syncwarp();

        unsigned pa[4][4];
#pragma unroll
        for (int ks = 0; ks < 4; ks++)
            ldsm_x4(pa[ks], psBase + 2u * ((wid * 16 + a_lr) * FP + ks * 16 + a_lc));
#pragma unroll
        for (int nj = 0; nj < 8; nj++) {
            unsigned vf[8];
            ldsm_x4_t(vf, vsBase + 2u * (lane * FP + nj * 8));
            ldsm_x4_t(vf + 4, vsBase + 2u * ((32 + lane) * FP + nj * 8));
#pragma unroll
            for (int ks = 0; ks < 4; ks++) {
                unsigned bb[2] = {vf[2 * ks], vf[2 * ks + 1]};
                mma_f16(o[nj], pa[ks], bb);
            }
        }
        __syncthreads();
    }

    __half* __restrict__ Ag = g_A + base;
    const float inv0 = 1.0f / l0, inv1 = 1.0f / l1;
#pragma unroll
    for (int nj = 0; nj < 8; nj++) {
        const int d = nj * 8 + 2 * t;
        *(__half2*)&Ag[(size_t)(q0 + qrow) * Dn + d] =
            __floats2half2_rn(o[nj][0] * inv0, o[nj][1] * inv0);
        *(__half2*)&Ag[(size_t)(q0 + qrow + 8) * Dn + d] =
            __floats2half2_rn(o[nj][2] * inv1, o[nj][3] * inv1);
    }
}

// ---------------------------------------------------------------------------
extern "C" void kernel_launch(void* const* d_in, const int* in_sizes, int n_in,
                              void* d_out, int out_size)
{
    const float* x  = (const float*)d_in[0];
    const float* Wq = (const float*)d_in[1];
    const float* Wk = (const float*)d_in[2];
    const float* Wv = (const float*)d_in[3];
    const float* Wo = (const float*)d_in[4];
    const float* bo = (const float*)d_in[5];
    float* out = (float*)d_out;

    cudaFuncSetAttribute(qkv_h_kernel,
                         cudaFuncAttributeMaxDynamicSharedMemorySize, GEMM_SMEM);
    cudaFuncSetAttribute(oproj_h_kernel,
                         cudaFuncAttributeMaxDynamicSharedMemorySize, GEMM_SMEM);

    xconv_kernel<<<(Bn * Tn * Cn) / 1024, 256>>>(x);
    wtrans_kernel<<<dim3(Cn / 32, Cn / 32, 4), dim3(32, 8)>>>(Wq, Wk, Wv, Wo);

    qkv_h_kernel<<<dim3(Cn / 128, (Bn * Tn) / 128, 3), 256, GEMM_SMEM>>>();

    flash_h_kernel<<<dim3(Tn / 64, Hn, Bn), 128>>>();

    oproj_h_kernel<<<dim3(Cn / 128, (Bn * Tn) / 128), 256, GEMM_SMEM>>>(bo, out);
}

// round 11
// speedup vs baseline: 1.2449x; 1.0182x over previous
#include <cuda_runtime.h>
#include <cuda_fp16.h>
#include <cstdint>

#define Bn 4
#define Tn 2048
#define Cn 1024
#define Hn 16
#define Dn 64

// Inter-kernel tensors in half, [B,H,T,D]
__device__ __half g_Q[Bn * Hn * Tn * Dn];
__device__ __half g_K[Bn * Hn * Tn * Dn];
__device__ __half g_V[Bn * Hn * Tn * Dn];
__device__ __half g_A[Bn * Hn * Tn * Dn];
__device__ __half g_Xh[Bn * Tn * Cn];         // half(x), row-major [B*T][C]
__device__ __half g_Wt[4][Cn * Cn];           // Wt[z][n][k] = half(W_z[k][n])

__device__ __forceinline__ void mma_f16(float* c, const unsigned* a, const unsigned* b) {
    asm volatile(
        "mma.sync.aligned.m16n8k16.row.col.f32.f16.f16.f32 "
        "{%0,%1,%2,%3}, {%4,%5,%6,%7}, {%8,%9}, {%0,%1,%2,%3};\n"
        : "+f"(c[0]), "+f"(c[1]), "+f"(c[2]), "+f"(c[3])
        : "r"(a[0]), "r"(a[1]), "r"(a[2]), "r"(a[3]), "r"(b[0]), "r"(b[1]));
}
__device__ __forceinline__ void ldsm_x4(unsigned* r, uint32_t addr) {
    asm volatile(
        "ldmatrix.sync.aligned.m8n8.x4.shared.b16 {%0,%1,%2,%3}, [%4];"
        : "=r"(r[0]), "=r"(r[1]), "=r"(r[2]), "=r"(r[3]) : "r"(addr));
}
__device__ __forceinline__ void ldsm_x4_t(unsigned* r, uint32_t addr) {
    asm volatile(
        "ldmatrix.sync.aligned.m8n8.x4.trans.shared.b16 {%0,%1,%2,%3}, [%4];"
        : "=r"(r[0]), "=r"(r[1]), "=r"(r[2]), "=r"(r[3]) : "r"(addr));
}
__device__ __forceinline__ void cp16(uint32_t dst, const void* src) {
    asm volatile("cp.async.cg.shared.global [%0], [%1], 16;" :: "r"(dst), "l"(src) : "memory");
}

// ---------------------------------------------------------------------------
// One-shot input conversion: g_Xh = half(x)
// ---------------------------------------------------------------------------
__global__ __launch_bounds__(256) void xconv_kernel(const float* __restrict__ X)
{
    const int i = (blockIdx.x * 256 + threadIdx.x) * 4;
    float4 v = *(const float4*)&X[i];
    __half2 h0 = __floats2half2_rn(v.x, v.y);
    __half2 h1 = __floats2half2_rn(v.z, v.w);
    *(uint2*)&g_Xh[i] = make_uint2(*(unsigned*)&h0, *(unsigned*)&h1);
}

// ---------------------------------------------------------------------------
// One-shot weight transpose: g_Wt[z][n][k] = half(W_z[k][n])
// ---------------------------------------------------------------------------
__global__ __launch_bounds__(256) void wtrans_kernel(
    const float* __restrict__ Wq, const float* __restrict__ Wk,
    const float* __restrict__ Wv, const float* __restrict__ Wo)
{
    __shared__ float tile[32][33];
    const int z = blockIdx.z;
    const float* __restrict__ W = (z == 0) ? Wq : (z == 1) ? Wk : (z == 2) ? Wv : Wo;
    const int x0 = blockIdx.x << 5, y0 = blockIdx.y << 5;
    const int tx = threadIdx.x, ty = threadIdx.y;
#pragma unroll
    for (int j = 0; j < 32; j += 8)
        tile[ty + j][tx] = W[(size_t)(y0 + ty + j) * Cn + x0 + tx];
    __syncthreads();
#pragma unroll
    for (int j = 0; j < 32; j += 8)
        g_Wt[z][(size_t)(x0 + ty + j) * Cn + y0 + tx] = __float2half_rn(tile[tx][ty + j]);
}

// ---------------------------------------------------------------------------
// fp16 GEMM: block 128x128, BK=32, 8 warps (warp 64x32), 3-stage cp.async.
// ---------------------------------------------------------------------------
#define QP 40
#define NST 3
#define STG_H (128 * QP)
#define GEMM_SMEM (2 * NST * STG_H * 2)

#define GEMM_COMPUTE()                                                          \
    do {                                                                        \
        const uint32_t so = 2u * (unsigned)(cur * STG_H);                       \
        _Pragma("unroll")                                                       \
        for (int ks = 0; ks < 2; ks++) {                                        \
            const int kk = ks << 4;                                             \
            unsigned bf[2][4];                                                  \
            _Pragma("unroll")                                                   \
            for (int p = 0; p < 2; p++) {                                       \
                const unsigned rn = warpn * 32 + p * 16 + b_lr;                 \
                ldsm_x4(bf[p], bBase + so + 2u * (rn * QP + kk + b_lc));        \
            }                                                                   \
            _Pragma("unroll")                                                   \
            for (int mi = 0; mi < 4; mi++) {                                    \
                unsigned a[4];                                                  \
                const unsigned rm = warpm * 64 + mi * 16 + a_lr;                \
                ldsm_x4(a, aBase + so + 2u * (rm * QP + kk + a_lc));            \
                _Pragma("unroll")                                               \
                for (int nj = 0; nj < 4; nj++) {                                \
                    unsigned bb[2] = {bf[nj >> 1][(nj & 1) * 2],                \
                                      bf[nj >> 1][(nj & 1) * 2 + 1]};           \
                    mma_f16(c[mi][nj], a, bb);                                  \
                }                                                               \
            }                                                                   \
        }                                                                       \
    } while (0)

__global__ __launch_bounds__(256, 2) void qkv_h_kernel()
{
    extern __shared__ __align__(16) __half smg[];
    __half* As = smg;
    __half* Bs = smg + NST * STG_H;

    const int z = blockIdx.z;
    const __half* __restrict__ Wt = g_Wt[z];
    __half* __restrict__ Y = (z == 0) ? g_Q : (z == 1) ? g_K : g_V;

    const int tid = threadIdx.x;
    const int lane = tid & 31, wid = tid >> 5;
    const int g = lane >> 2, t = lane & 3;
    const int warpm = wid >> 2, warpn = wid & 3;
    const int m0 = blockIdx.y << 7, n0 = blockIdx.x << 7;

    const int row = tid >> 1, e = tid & 1;
    const __half* Asrc = &g_Xh[(size_t)(m0 + row) * Cn + e * 16];
    const __half* Bsrc = &Wt[(size_t)(n0 + row) * Cn + e * 16];
    const uint32_t aSm = (uint32_t)__cvta_generic_to_shared(&As[row * QP + e * 16]);
    const uint32_t bSm = (uint32_t)__cvta_generic_to_shared(&Bs[row * QP + e * 16]);

    auto stage = [&](int stg, int k0) {
        const uint32_t ao = aSm + 2u * (unsigned)(stg * STG_H);
        cp16(ao, Asrc + k0);
        cp16(ao + 16, Asrc + k0 + 8);
        const uint32_t bo2 = bSm + 2u * (unsigned)(stg * STG_H);
        cp16(bo2, Bsrc + k0);
        cp16(bo2 + 16, Bsrc + k0 + 8);
        asm volatile("cp.async.commit_group;" ::: "memory");
    };

    float c[4][4][4] = {};
    stage(0, 0);
    stage(1, 32);

    const unsigned a_lr = (lane & 7) + (((lane >> 3) & 1) << 3);
    const unsigned a_lc = ((lane >> 4) & 1) << 3;
    const unsigned b_lr = (((lane >> 4) & 1) << 3) + (lane & 7);
    const unsigned b_lc = ((lane >> 3) & 1) << 3;
    const uint32_t aBase = (uint32_t)__cvta_generic_to_shared(As);
    const uint32_t bBase = (uint32_t)__cvta_generic_to_shared(Bs);

    for (int it = 0; it < Cn / 32; ++it) {
        const int cur = it % NST;
        if (it + 2 < Cn / 32)
            asm volatile("cp.async.wait_group 1;" ::: "memory");
        else
            asm volatile("cp.async.wait_group 0;" ::: "memory");
        __syncthreads();
        GEMM_COMPUTE();
        if (it + 2 < Cn / 32) stage((it + 2) % NST, (it + 2) * 32);
        __syncthreads();
    }

#pragma unroll
    for (int mi = 0; mi < 4; mi++) {
#pragma unroll
        for (int r = 0; r < 2; r++) {
            const int mrow = m0 + warpm * 64 + mi * 16 + g + 8 * r;
            const int b_ = mrow >> 11, t_ = mrow & (Tn - 1);
#pragma unroll
            for (int nj = 0; nj < 4; nj++) {
                const int n = n0 + warpn * 32 + nj * 8 + 2 * t;
                const int h = n >> 6, d = n & 63;
                __half2 hv = __floats2half2_rn(c[mi][nj][2 * r], c[mi][nj][2 * r + 1]);
                *(__half2*)&Y[(size_t)((b_ * Hn + h) * Tn + t_) * Dn + d] = hv;
            }
        }
    }
}

__global__ __launch_bounds__(256, 2) void oproj_h_kernel(
    const float* __restrict__ bo, float* __restrict__ out)
{
    extern __shared__ __align__(16) __half smg[];
    __half* As = smg;
    __half* Bs = smg + NST * STG_H;
    const __half* __restrict__ Wt = g_Wt[3];

    const int tid = threadIdx.x;
    const int lane = tid & 31, wid = tid >> 5;
    const int g = lane >> 2, t = lane & 3;
    const int warpm = wid >> 2, warpn = wid & 3;
    const int m0 = blockIdx.y << 7, n0 = blockIdx.x << 7;

    const int row = tid >> 1, e = tid & 1;
    const int m = m0 + row;
    const int mb = m >> 11, mt = m & (Tn - 1);
    const __half* aRowBase = &g_A[((size_t)(mb * Hn) * Tn + mt) * Dn + e * 16];
    const __half* Bsrc = &Wt[(size_t)(n0 + row) * Cn + e * 16];
    const uint32_t aSm = (uint32_t)__cvta_generic_to_shared(&As[row * QP + e * 16]);
    const uint32_t bSm = (uint32_t)__cvta_generic_to_shared(&Bs[row * QP + e * 16]);

    auto stage = [&](int stg, int k0) {
        const __half* as = aRowBase + (size_t)(k0 >> 6) * Tn * Dn + (k0 & 63);
        const uint32_t ao = aSm + 2u * (unsigned)(stg * STG_H);
        cp16(ao, as);
        cp16(ao + 16, as + 8);
        const uint32_t bo2 = bSm + 2u * (unsigned)(stg * STG_H);
        cp16(bo2, Bsrc + k0);
        cp16(bo2 + 16, Bsrc + k0 + 8);
        asm volatile("cp.async.commit_group;" ::: "memory");
    };

    float c[4][4][4] = {};
    stage(0, 0);
    stage(1, 32);

    const unsigned a_lr = (lane & 7) + (((lane >> 3) & 1) << 3);
    const unsigned a_lc = ((lane >> 4) & 1) << 3;
    const unsigned b_lr = (((lane >> 4) & 1) << 3) + (lane & 7);
    const unsigned b_lc = ((lane >> 3) & 1) << 3;
    const uint32_t aBase = (uint32_t)__cvta_generic_to_shared(As);
    const uint32_t bBase = (uint32_t)__cvta_generic_to_shared(Bs);

    for (int it = 0; it < Cn / 32; ++it) {
        const int cur = it % NST;
        if (it + 2 < Cn / 32)
            asm volatile("cp.async.wait_group 1;" ::: "memory");
        else
            asm volatile("cp.async.wait_group 0;" ::: "memory");
        __syncthreads();
        GEMM_COMPUTE();
        if (it + 2 < Cn / 32) stage((it + 2) % NST, (it + 2) * 32);
        __syncthreads();
    }

#pragma unroll
    for (int mi = 0; mi < 4; mi++) {
#pragma unroll
        for (int r = 0; r < 2; r++) {
            const int mrow = m0 + warpm * 64 + mi * 16 + g + 8 * r;
#pragma unroll
            for (int nj = 0; nj < 4; nj++) {
                const int n = n0 + warpn * 32 + nj * 8 + 2 * t;
                float2 bias = *(const float2*)&bo[n];
                float2 v = {c[mi][nj][2 * r] + bias.x, c[mi][nj][2 * r + 1] + bias.y};
                *(float2*)&out[(size_t)mrow * Cn + n] = v;
            }
        }
    }
}

// ---------------------------------------------------------------------------
// Flash attention fp16: Br=Bc=64, 4 warps, Q frags in registers,
// double-buffered cp.async K/V staging.
// ---------------------------------------------------------------------------
#define FP 72
#define KV_STG (64 * FP)   // halves per K (or V) buffer

__global__ __launch_bounds__(128, 4) void flash_h_kernel()
{
    __shared__ __half Ks[2][64][FP];
    __shared__ __half Vs[2][64][FP];
    __shared__ __half Ps[64][FP];

    const int qb = blockIdx.x;
    const int h = blockIdx.y, b = blockIdx.z;
    const int tid = threadIdx.x;
    const int lane = tid & 31, wid = tid >> 5;
    const int g = lane >> 2, t = lane & 3;
    const int q0 = qb << 6;
    const int qrow = (wid << 4) + g;

    const size_t base = (size_t)((b * Hn + h) * Tn) * Dn;
    const __half* __restrict__ Qg = g_Q + base;
    const __half* __restrict__ Kg = g_K + base;
    const __half* __restrict__ Vg = g_V + base;

    const int srow = tid >> 1, se = tid & 1;
    const uint32_t ksBase = (uint32_t)__cvta_generic_to_shared(&Ks[0][0][0]);
    const uint32_t vsBase = (uint32_t)__cvta_generic_to_shared(&Vs[0][0][0]);
    const uint32_t psBase = (uint32_t)__cvta_generic_to_shared(&Ps[0][0]);

    // stage K/V tile (one commit group per kv-tile)
    const uint32_t kDst = ksBase + 2u * (srow * FP + se * 32);
    const uint32_t vDst = vsBase + 2u * (srow * FP + se * 32);
    auto stageKV = [&](int buf, int k0) {
        const __half* ks = &Kg[(size_t)(k0 + srow) * Dn + se * 32];
        const __half* vs = &Vg[(size_t)(k0 + srow) * Dn + se * 32];
        const uint32_t off = 2u * (unsigned)(buf * KV_STG);
#pragma unroll
        for (int j = 0; j < 4; j++) {
            cp16(kDst + off + j * 16, ks + j * 8);
            cp16(vDst + off + j * 16, vs + j * 8);
        }
        asm volatile("cp.async.commit_group;" ::: "memory");
    };

    // stage Q into Ps, lift A-fragments to registers
    {
        const uint4* qp = (const uint4*)&Qg[(size_t)(q0 + srow) * Dn + se * 32];
#pragma unroll
        for (int j = 0; j < 4; j++)
            *(uint4*)&Ps[srow][se * 32 + j * 8] = qp[j];
    }
    stageKV(0, 0);
    if (qb > 0) stageKV(1, 64);
    __syncthreads();

    const unsigned a_lr = (lane & 7) + (((lane >> 3) & 1) << 3);
    const unsigned a_lc = ((lane >> 4) & 1) << 3;

    unsigned qa[4][4];
#pragma unroll
    for (int ks = 0; ks < 4; ks++)
        ldsm_x4(qa[ks], psBase + 2u * ((wid * 16 + a_lr) * FP + ks * 16 + a_lc));

    float o[8][4] = {};
    float mv0 = -1e30f, mv1 = -1e30f, l0 = 0.0f, l1 = 0.0f;

    for (int kb = 0; kb <= qb; kb++) {
        if (kb < qb)
            asm volatile("cp.async.wait_group 1;" ::: "memory");
        else
            asm volatile("cp.async.wait_group 0;" ::: "memory");
        __syncthreads();

        const uint32_t so = 2u * (unsigned)((kb & 1) * KV_STG);

        // ---- S = Q @ K^T ----
        float s[8][4] = {};
#pragma unroll
        for (int nj = 0; nj < 8; nj++) {
            unsigned bf[8];
            const uint32_t ad = ksBase + so +
                2u * ((nj * 8 + (lane & 7)) * FP + (lane >> 3) * 8);
            ldsm_x4(bf, ad);
            ldsm_x4(bf + 4, ad + 64);
#pragma unroll
            for (int ks = 0; ks < 4; ks++) {
                unsigned bb[2] = {bf[2 * ks], bf[2 * ks + 1]};
                mma_f16(s[nj], qa[ks], bb);
            }
        }

        // ---- scale + causal mask ----
        const bool diag = (kb == qb);
#pragma unroll
        for (int nj = 0; nj < 8; nj++) {
#pragma unroll
            for (int e2 = 0; e2 < 4; e2++) s[nj][e2] *= 0.125f;
            if (diag) {
                const int col0 = nj * 8 + 2 * t, col1 = col0 + 1;
                if (col0 > qrow) s[nj][0] = -1e30f;
                if (col1 > qrow) s[nj][1] = -1e30f;
                if (col0 > qrow + 8) s[nj][2] = -1e30f;
                if (col1 > qrow + 8) s[nj][3] = -1e30f;
            }
        }

        // ---- online softmax ----
        float mt0 = -1e30f, mt1 = -1e30f;
#pragma unroll
        for (int nj = 0; nj < 8; nj++) {
            mt0 = fmaxf(mt0, fmaxf(s[nj][0], s[nj][1]));
            mt1 = fmaxf(mt1, fmaxf(s[nj][2], s[nj][3]));
        }
        mt0 = fmaxf(mt0, __shfl_xor_sync(0xffffffffu, mt0, 1));
        mt0 = fmaxf(mt0, __shfl_xor_sync(0xffffffffu, mt0, 2));
        mt1 = fmaxf(mt1, __shfl_xor_sync(0xffffffffu, mt1, 1));
        mt1 = fmaxf(mt1, __shfl_xor_sync(0xffffffffu, mt1, 2));

        const float mn0 = fmaxf(mv0, mt0);
        const float mn1 = fmaxf(mv1, mt1);
        float sum0 = 0.0f, sum1 = 0.0f;
#pragma unroll
        for (int nj = 0; nj < 8; nj++) {
            float p0 = __expf(s[nj][0] - mn0);
            float p1 = __expf(s[nj][1] - mn0);
            float p2 = __expf(s[nj][2] - mn1);
            float p3 = __expf(s[nj][3] - mn1);
            sum0 += p0 + p1;
            sum1 += p2 + p3;
            *(__half2*)&Ps[qrow][nj * 8 + 2 * t] = __floats2half2_rn(p0, p1);
            *(__half2*)&Ps[qrow + 8][nj * 8 + 2 * t] = __floats2half2_rn(p2, p3);
        }
        sum0 += __shfl_xor_sync(0xffffffffu, sum0, 1);
        sum0 += __shfl_xor_sync(0xffffffffu, sum0, 2);
        sum1 += __shfl_xor_sync(0xffffffffu, sum1, 1);
        sum1 += __shfl_xor_sync(0xffffffffu, sum1, 2);

        const float cf0 = __expf(mv0 - mn0);
        const float cf1 = __expf(mv1 - mn1);
        l0 = l0 * cf0 + sum0;
        l1 = l1 * cf1 + sum1;
        mv0 = mn0;
        mv1 = mn1;
#pragma unroll
        for (int nj = 0; nj < 8; nj++) {
            o[nj][0] *= cf0; o[nj][1] *= cf0;
            o[nj][2] *= cf1; o[nj][3] *= cf1;
        }
        __syncwarp();

        // ---- O += P @ V ----
        unsigned pa[4][4];
#pragma unroll
        for (int ks = 0; ks < 4; ks++)
            ldsm_x4(pa[ks], psBase + 2u * ((wid * 16 + a_lr) * FP + ks * 16 + a_lc));
#pragma unroll
        for (int nj = 0; nj < 8; nj++) {
            unsigned vf[8];
            ldsm_x4_t(vf, vsBase + so + 2u * (lane * FP + nj * 8));
            ldsm_x4_t(vf + 4, vsBase + so + 2u * ((32 + lane) * FP + nj * 8));
#pragma unroll
            for (int ks = 0; ks < 4; ks++) {
                unsigned bb[2] = {vf[2 * ks], vf[2 * ks + 1]};
                mma_f16(o[nj], pa[ks], bb);
            }
        }
        __syncthreads();
        if (kb + 2 <= qb) stageKV(kb & 1, (kb + 2) << 6);
    }

    // ---- normalize + write g_A (half) ----
    __half* __restrict__ Ag = g_A + base;
    const float inv0 = 1.0f / l0, inv1 = 1.0f / l1;
#pragma unroll
    for (int nj = 0; nj < 8; nj++) {
        const int d = nj * 8 + 2 * t;
        *(__half2*)&Ag[(size_t)(q0 + qrow) * Dn + d] =
            __floats2half2_rn(o[nj][0] * inv0, o[nj][1] * inv0);
        *(__half2*)&Ag[(size_t)(q0 + qrow + 8) * Dn + d] =
            __floats2half2_rn(o[nj][2] * inv1, o[nj][3] * inv1);
    }
}

// ---------------------------------------------------------------------------
extern "C" void kernel_launch(void* const* d_in, const int* in_sizes, int n_in,
                              void* d_out, int out_size)
{
    const float* x  = (const float*)d_in[0];
    const float* Wq = (const float*)d_in[1];
    const float* Wk = (const float*)d_in[2];
    const float* Wv = (const float*)d_in[3];
    const float* Wo = (const float*)d_in[4];
    const float* bo = (const float*)d_in[5];
    float* out = (float*)d_out;

    cudaFuncSetAttribute(qkv_h_kernel,
                         cudaFuncAttributeMaxDynamicSharedMemorySize, GEMM_SMEM);
    cudaFuncSetAttribute(oproj_h_kernel,
                         cudaFuncAttributeMaxDynamicSharedMemorySize, GEMM_SMEM);

    xconv_kernel<<<(Bn * Tn * Cn) / 1024, 256>>>(x);
    wtrans_kernel<<<dim3(Cn / 32, Cn / 32, 4), dim3(32, 8)>>>(Wq, Wk, Wv, Wo);

    qkv_h_kernel<<<dim3(Cn / 128, (Bn * Tn) / 128, 3), 256, GEMM_SMEM>>>();

    flash_h_kernel<<<dim3(Tn / 64, Hn, Bn), 128>>>();

    oproj_h_kernel<<<dim3(Cn / 128, (Bn * Tn) / 128), 256, GEMM_SMEM>>>(bo, out);
}

// round 12
// speedup vs baseline: 1.2687x; 1.0190x over previous
#include <cuda_runtime.h>
#include <cuda_fp16.h>
#include <cstdint>

#define Bn 4
#define Tn 2048
#define Cn 1024
#define Hn 16
#define Dn 64

// Inter-kernel tensors in half, [B,H,T,D]
__device__ __half g_Q[Bn * Hn * Tn * Dn];
__device__ __half g_K[Bn * Hn * Tn * Dn];
__device__ __half g_V[Bn * Hn * Tn * Dn];
__device__ __half g_A[Bn * Hn * Tn * Dn];
__device__ __half g_Xh[Bn * Tn * Cn];         // half(x), row-major [B*T][C]
__device__ __half g_Wt[4][Cn * Cn];           // Wt[z][n][k] = half(W_z[k][n])

__device__ __forceinline__ unsigned h2u(float a, float b) {
    __half2 h = __floats2half2_rn(a, b);
    return *(unsigned*)&h;
}
__device__ __forceinline__ void mma_f16(float* c, const unsigned* a, const unsigned* b) {
    asm volatile(
        "mma.sync.aligned.m16n8k16.row.col.f32.f16.f16.f32 "
        "{%0,%1,%2,%3}, {%4,%5,%6,%7}, {%8,%9}, {%0,%1,%2,%3};\n"
        : "+f"(c[0]), "+f"(c[1]), "+f"(c[2]), "+f"(c[3])
        : "r"(a[0]), "r"(a[1]), "r"(a[2]), "r"(a[3]), "r"(b[0]), "r"(b[1]));
}
__device__ __forceinline__ void ldsm_x4(unsigned* r, uint32_t addr) {
    asm volatile(
        "ldmatrix.sync.aligned.m8n8.x4.shared.b16 {%0,%1,%2,%3}, [%4];"
        : "=r"(r[0]), "=r"(r[1]), "=r"(r[2]), "=r"(r[3]) : "r"(addr));
}
__device__ __forceinline__ void ldsm_x4_t(unsigned* r, uint32_t addr) {
    asm volatile(
        "ldmatrix.sync.aligned.m8n8.x4.trans.shared.b16 {%0,%1,%2,%3}, [%4];"
        : "=r"(r[0]), "=r"(r[1]), "=r"(r[2]), "=r"(r[3]) : "r"(addr));
}
__device__ __forceinline__ void cp16(uint32_t dst, const void* src) {
    asm volatile("cp.async.cg.shared.global [%0], [%1], 16;" :: "r"(dst), "l"(src) : "memory");
}

// ---------------------------------------------------------------------------
// One-shot input conversion: g_Xh = half(x)
// ---------------------------------------------------------------------------
__global__ __launch_bounds__(256) void xconv_kernel(const float* __restrict__ X)
{
    const int i = (blockIdx.x * 256 + threadIdx.x) * 4;
    float4 v = *(const float4*)&X[i];
    __half2 h0 = __floats2half2_rn(v.x, v.y);
    __half2 h1 = __floats2half2_rn(v.z, v.w);
    *(uint2*)&g_Xh[i] = make_uint2(*(unsigned*)&h0, *(unsigned*)&h1);
}

// ---------------------------------------------------------------------------
// One-shot weight transpose: g_Wt[z][n][k] = half(W_z[k][n])
// ---------------------------------------------------------------------------
__global__ __launch_bounds__(256) void wtrans_kernel(
    const float* __restrict__ Wq, const float* __restrict__ Wk,
    const float* __restrict__ Wv, const float* __restrict__ Wo)
{
    __shared__ float tile[32][33];
    const int z = blockIdx.z;
    const float* __restrict__ W = (z == 0) ? Wq : (z == 1) ? Wk : (z == 2) ? Wv : Wo;
    const int x0 = blockIdx.x << 5, y0 = blockIdx.y << 5;
    const int tx = threadIdx.x, ty = threadIdx.y;
#pragma unroll
    for (int j = 0; j < 32; j += 8)
        tile[ty + j][tx] = W[(size_t)(y0 + ty + j) * Cn + x0 + tx];
    __syncthreads();
#pragma unroll
    for (int j = 0; j < 32; j += 8)
        g_Wt[z][(size_t)(x0 + ty + j) * Cn + y0 + tx] = __float2half_rn(tile[tx][ty + j]);
}

// ---------------------------------------------------------------------------
// fp16 GEMM: block 128x128, BK=32, 8 warps (warp 64x32), 3-stage cp.async.
// ---------------------------------------------------------------------------
#define QP 40
#define NST 3
#define STG_H (128 * QP)
#define GEMM_SMEM (2 * NST * STG_H * 2)

#define GEMM_COMPUTE()                                                          \
    do {                                                                        \
        const uint32_t so = 2u * (unsigned)(cur * STG_H);                       \
        _Pragma("unroll")                                                       \
        for (int ks = 0; ks < 2; ks++) {                                        \
            const int kk = ks << 4;                                             \
            unsigned bf[2][4];                                                  \
            _Pragma("unroll")                                                   \
            for (int p = 0; p < 2; p++) {                                       \
                const unsigned rn = warpn * 32 + p * 16 + b_lr;                 \
                ldsm_x4(bf[p], bBase + so + 2u * (rn * QP + kk + b_lc));        \
            }                                                                   \
            _Pragma("unroll")                                                   \
            for (int mi = 0; mi < 4; mi++) {                                    \
                unsigned a[4];                                                  \
                const unsigned rm = warpm * 64 + mi * 16 + a_lr;                \
                ldsm_x4(a, aBase + so + 2u * (rm * QP + kk + a_lc));            \
                _Pragma("unroll")                                               \
                for (int nj = 0; nj < 4; nj++) {                                \
                    unsigned bb[2] = {bf[nj >> 1][(nj & 1) * 2],                \
                                      bf[nj >> 1][(nj & 1) * 2 + 1]};           \
                    mma_f16(c[mi][nj], a, bb);                                  \
                }                                                               \
            }                                                                   \
        }                                                                       \
    } while (0)

__global__ __launch_bounds__(256, 2) void qkv_h_kernel()
{
    extern __shared__ __align__(16) __half smg[];
    __half* As = smg;
    __half* Bs = smg + NST * STG_H;

    const int z = blockIdx.z;
    const __half* __restrict__ Wt = g_Wt[z];
    __half* __restrict__ Y = (z == 0) ? g_Q : (z == 1) ? g_K : g_V;

    const int tid = threadIdx.x;
    const int lane = tid & 31, wid = tid >> 5;
    const int g = lane >> 2, t = lane & 3;
    const int warpm = wid >> 2, warpn = wid & 3;
    const int m0 = blockIdx.y << 7, n0 = blockIdx.x << 7;

    const int row = tid >> 1, e = tid & 1;
    const __half* Asrc = &g_Xh[(size_t)(m0 + row) * Cn + e * 16];
    const __half* Bsrc = &Wt[(size_t)(n0 + row) * Cn + e * 16];
    const uint32_t aSm = (uint32_t)__cvta_generic_to_shared(&As[row * QP + e * 16]);
    const uint32_t bSm = (uint32_t)__cvta_generic_to_shared(&Bs[row * QP + e * 16]);

    auto stage = [&](int stg, int k0) {
        const uint32_t ao = aSm + 2u * (unsigned)(stg * STG_H);
        cp16(ao, Asrc + k0);
        cp16(ao + 16, Asrc + k0 + 8);
        const uint32_t bo2 = bSm + 2u * (unsigned)(stg * STG_H);
        cp16(bo2, Bsrc + k0);
        cp16(bo2 + 16, Bsrc + k0 + 8);
        asm volatile("cp.async.commit_group;" ::: "memory");
    };

    float c[4][4][4] = {};
    stage(0, 0);
    stage(1, 32);

    const unsigned a_lr = (lane & 7) + (((lane >> 3) & 1) << 3);
    const unsigned a_lc = ((lane >> 4) & 1) << 3;
    const unsigned b_lr = (((lane >> 4) & 1) << 3) + (lane & 7);
    const unsigned b_lc = ((lane >> 3) & 1) << 3;
    const uint32_t aBase = (uint32_t)__cvta_generic_to_shared(As);
    const uint32_t bBase = (uint32_t)__cvta_generic_to_shared(Bs);

    for (int it = 0; it < Cn / 32; ++it) {
        const int cur = it % NST;
        if (it + 2 < Cn / 32)
            asm volatile("cp.async.wait_group 1;" ::: "memory");
        else
            asm volatile("cp.async.wait_group 0;" ::: "memory");
        __syncthreads();
        GEMM_COMPUTE();
        if (it + 2 < Cn / 32) stage((it + 2) % NST, (it + 2) * 32);
        __syncthreads();
    }

#pragma unroll
    for (int mi = 0; mi < 4; mi++) {
#pragma unroll
        for (int r = 0; r < 2; r++) {
            const int mrow = m0 + warpm * 64 + mi * 16 + g + 8 * r;
            const int b_ = mrow >> 11, t_ = mrow & (Tn - 1);
#pragma unroll
            for (int nj = 0; nj < 4; nj++) {
                const int n = n0 + warpn * 32 + nj * 8 + 2 * t;
                const int h = n >> 6, d = n & 63;
                __half2 hv = __floats2half2_rn(c[mi][nj][2 * r], c[mi][nj][2 * r + 1]);
                *(__half2*)&Y[(size_t)((b_ * Hn + h) * Tn + t_) * Dn + d] = hv;
            }
        }
    }
}

__global__ __launch_bounds__(256, 2) void oproj_h_kernel(
    const float* __restrict__ bo, float* __restrict__ out)
{
    extern __shared__ __align__(16) __half smg[];
    __half* As = smg;
    __half* Bs = smg + NST * STG_H;
    const __half* __restrict__ Wt = g_Wt[3];

    const int tid = threadIdx.x;
    const int lane = tid & 31, wid = tid >> 5;
    const int g = lane >> 2, t = lane & 3;
    const int warpm = wid >> 2, warpn = wid & 3;
    const int m0 = blockIdx.y << 7, n0 = blockIdx.x << 7;

    const int row = tid >> 1, e = tid & 1;
    const int m = m0 + row;
    const int mb = m >> 11, mt = m & (Tn - 1);
    const __half* aRowBase = &g_A[((size_t)(mb * Hn) * Tn + mt) * Dn + e * 16];
    const __half* Bsrc = &Wt[(size_t)(n0 + row) * Cn + e * 16];
    const uint32_t aSm = (uint32_t)__cvta_generic_to_shared(&As[row * QP + e * 16]);
    const uint32_t bSm = (uint32_t)__cvta_generic_to_shared(&Bs[row * QP + e * 16]);

    auto stage = [&](int stg, int k0) {
        const __half* as = aRowBase + (size_t)(k0 >> 6) * Tn * Dn + (k0 & 63);
        const uint32_t ao = aSm + 2u * (unsigned)(stg * STG_H);
        cp16(ao, as);
        cp16(ao + 16, as + 8);
        const uint32_t bo2 = bSm + 2u * (unsigned)(stg * STG_H);
        cp16(bo2, Bsrc + k0);
        cp16(bo2 + 16, Bsrc + k0 + 8);
        asm volatile("cp.async.commit_group;" ::: "memory");
    };

    float c[4][4][4] = {};
    stage(0, 0);
    stage(1, 32);

    const unsigned a_lr = (lane & 7) + (((lane >> 3) & 1) << 3);
    const unsigned a_lc = ((lane >> 4) & 1) << 3;
    const unsigned b_lr = (((lane >> 4) & 1) << 3) + (lane & 7);
    const unsigned b_lc = ((lane >> 3) & 1) << 3;
    const uint32_t aBase = (uint32_t)__cvta_generic_to_shared(As);
    const uint32_t bBase = (uint32_t)__cvta_generic_to_shared(Bs);

    for (int it = 0; it < Cn / 32; ++it) {
        const int cur = it % NST;
        if (it + 2 < Cn / 32)
            asm volatile("cp.async.wait_group 1;" ::: "memory");
        else
            asm volatile("cp.async.wait_group 0;" ::: "memory");
        __syncthreads();
        GEMM_COMPUTE();
        if (it + 2 < Cn / 32) stage((it + 2) % NST, (it + 2) * 32);
        __syncthreads();
    }

#pragma unroll
    for (int mi = 0; mi < 4; mi++) {
#pragma unroll
        for (int r = 0; r < 2; r++) {
            const int mrow = m0 + warpm * 64 + mi * 16 + g + 8 * r;
#pragma unroll
            for (int nj = 0; nj < 4; nj++) {
                const int n = n0 + warpn * 32 + nj * 8 + 2 * t;
                float2 bias = *(const float2*)&bo[n];
                float2 v = {c[mi][nj][2 * r] + bias.x, c[mi][nj][2 * r + 1] + bias.y};
                *(float2*)&out[(size_t)mrow * Cn + n] = v;
            }
        }
    }
}

// ---------------------------------------------------------------------------
// Flash attention fp16: Br=Bc=64, 4 warps, Q frags in registers,
// double-buffered cp.async K/V staging, P kept in registers (C->A identity).
// ---------------------------------------------------------------------------
#define FP 72
#define KV_STG (64 * FP)   // halves per K (or V) buffer

__global__ __launch_bounds__(128, 4) void flash_h_kernel()
{
    __shared__ __half Ks[2][64][FP];
    __shared__ __half Vs[2][64][FP];
    __shared__ __half Ps[64][FP];   // Q staging only

    const int qb = blockIdx.x;
    const int h = blockIdx.y, b = blockIdx.z;
    const int tid = threadIdx.x;
    const int lane = tid & 31, wid = tid >> 5;
    const int g = lane >> 2, t = lane & 3;
    const int q0 = qb << 6;
    const int qrow = (wid << 4) + g;

    const size_t base = (size_t)((b * Hn + h) * Tn) * Dn;
    const __half* __restrict__ Qg = g_Q + base;
    const __half* __restrict__ Kg = g_K + base;
    const __half* __restrict__ Vg = g_V + base;

    const int srow = tid >> 1, se = tid & 1;
    const uint32_t ksBase = (uint32_t)__cvta_generic_to_shared(&Ks[0][0][0]);
    const uint32_t vsBase = (uint32_t)__cvta_generic_to_shared(&Vs[0][0][0]);
    const uint32_t psBase = (uint32_t)__cvta_generic_to_shared(&Ps[0][0]);

    const uint32_t kDst = ksBase + 2u * (srow * FP + se * 32);
    const uint32_t vDst = vsBase + 2u * (srow * FP + se * 32);
    auto stageKV = [&](int buf, int k0) {
        const __half* ks = &Kg[(size_t)(k0 + srow) * Dn + se * 32];
        const __half* vs = &Vg[(size_t)(k0 + srow) * Dn + se * 32];
        const uint32_t off = 2u * (unsigned)(buf * KV_STG);
#pragma unroll
        for (int j = 0; j < 4; j++) {
            cp16(kDst + off + j * 16, ks + j * 8);
            cp16(vDst + off + j * 16, vs + j * 8);
        }
        asm volatile("cp.async.commit_group;" ::: "memory");
    };

    // stage Q into Ps, lift A-fragments to registers
    {
        const uint4* qp = (const uint4*)&Qg[(size_t)(q0 + srow) * Dn + se * 32];
#pragma unroll
        for (int j = 0; j < 4; j++)
            *(uint4*)&Ps[srow][se * 32 + j * 8] = qp[j];
    }
    stageKV(0, 0);
    if (qb > 0) stageKV(1, 64);
    __syncthreads();

    const unsigned a_lr = (lane & 7) + (((lane >> 3) & 1) << 3);
    const unsigned a_lc = ((lane >> 4) & 1) << 3;

    unsigned qa[4][4];
#pragma unroll
    for (int ks = 0; ks < 4; ks++)
        ldsm_x4(qa[ks], psBase + 2u * ((wid * 16 + a_lr) * FP + ks * 16 + a_lc));

    float o[8][4] = {};
    float mv0 = -1e30f, mv1 = -1e30f, l0 = 0.0f, l1 = 0.0f;

    for (int kb = 0; kb <= qb; kb++) {
        if (kb < qb)
            asm volatile("cp.async.wait_group 1;" ::: "memory");
        else
            asm volatile("cp.async.wait_group 0;" ::: "memory");
        __syncthreads();

        const uint32_t so = 2u * (unsigned)((kb & 1) * KV_STG);

        // ---- S = Q @ K^T ----
        float s[8][4] = {};
#pragma unroll
        for (int nj = 0; nj < 8; nj++) {
            unsigned bf[8];
            const uint32_t ad = ksBase + so +
                2u * ((nj * 8 + (lane & 7)) * FP + (lane >> 3) * 8);
            ldsm_x4(bf, ad);
            ldsm_x4(bf + 4, ad + 64);
#pragma unroll
            for (int ks = 0; ks < 4; ks++) {
                unsigned bb[2] = {bf[2 * ks], bf[2 * ks + 1]};
                mma_f16(s[nj], qa[ks], bb);
            }
        }

        // ---- scale + causal mask ----
        const bool diag = (kb == qb);
#pragma unroll
        for (int nj = 0; nj < 8; nj++) {
#pragma unroll
            for (int e2 = 0; e2 < 4; e2++) s[nj][e2] *= 0.125f;
            if (diag) {
                const int col0 = nj * 8 + 2 * t, col1 = col0 + 1;
                if (col0 > qrow) s[nj][0] = -1e30f;
                if (col1 > qrow) s[nj][1] = -1e30f;
                if (col0 > qrow + 8) s[nj][2] = -1e30f;
                if (col1 > qrow + 8) s[nj][3] = -1e30f;
            }
        }

        // ---- online softmax (P stays in registers) ----
        float mt0 = -1e30f, mt1 = -1e30f;
#pragma unroll
        for (int nj = 0; nj < 8; nj++) {
            mt0 = fmaxf(mt0, fmaxf(s[nj][0], s[nj][1]));
            mt1 = fmaxf(mt1, fmaxf(s[nj][2], s[nj][3]));
        }
        mt0 = fmaxf(mt0, __shfl_xor_sync(0xffffffffu, mt0, 1));
        mt0 = fmaxf(mt0, __shfl_xor_sync(0xffffffffu, mt0, 2));
        mt1 = fmaxf(mt1, __shfl_xor_sync(0xffffffffu, mt1, 1));
        mt1 = fmaxf(mt1, __shfl_xor_sync(0xffffffffu, mt1, 2));

        const float mn0 = fmaxf(mv0, mt0);
        const float mn1 = fmaxf(mv1, mt1);
        float sum0 = 0.0f, sum1 = 0.0f;
#pragma unroll
        for (int nj = 0; nj < 8; nj++) {
            s[nj][0] = __expf(s[nj][0] - mn0);
            s[nj][1] = __expf(s[nj][1] - mn0);
            s[nj][2] = __expf(s[nj][2] - mn1);
            s[nj][3] = __expf(s[nj][3] - mn1);
            sum0 += s[nj][0] + s[nj][1];
            sum1 += s[nj][2] + s[nj][3];
        }
        sum0 += __shfl_xor_sync(0xffffffffu, sum0, 1);
        sum0 += __shfl_xor_sync(0xffffffffu, sum0, 2);
        sum1 += __shfl_xor_sync(0xffffffffu, sum1, 1);
        sum1 += __shfl_xor_sync(0xffffffffu, sum1, 2);

        const float cf0 = __expf(mv0 - mn0);
        const float cf1 = __expf(mv1 - mn1);
        l0 = l0 * cf0 + sum0;
        l1 = l1 * cf1 + sum1;
        mv0 = mn0;
        mv1 = mn1;
#pragma unroll
        for (int nj = 0; nj < 8; nj++) {
            o[nj][0] *= cf0; o[nj][1] *= cf0;
            o[nj][2] *= cf1; o[nj][3] *= cf1;
        }

        // ---- pack P fragments directly from C layout (no smem) ----
        unsigned pa[4][4];
#pragma unroll
        for (int ks = 0; ks < 4; ks++) {
            pa[ks][0] = h2u(s[2 * ks][0], s[2 * ks][1]);
            pa[ks][1] = h2u(s[2 * ks][2], s[2 * ks][3]);
            pa[ks][2] = h2u(s[2 * ks + 1][0], s[2 * ks + 1][1]);
            pa[ks][3] = h2u(s[2 * ks + 1][2], s[2 * ks + 1][3]);
        }

        // ---- O += P @ V ----
#pragma unroll
        for (int nj = 0; nj < 8; nj++) {
            unsigned vf[8];
            ldsm_x4_t(vf, vsBase + so + 2u * (lane * FP + nj * 8));
            ldsm_x4_t(vf + 4, vsBase + so + 2u * ((32 + lane) * FP + nj * 8));
#pragma unroll
            for (int ks = 0; ks < 4; ks++) {
                unsigned bb[2] = {vf[2 * ks], vf[2 * ks + 1]};
                mma_f16(o[nj], pa[ks], bb);
            }
        }
        __syncthreads();
        if (kb + 2 <= qb) stageKV(kb & 1, (kb + 2) << 6);
    }

    // ---- normalize + write g_A (half) ----
    __half* __restrict__ Ag = g_A + base;
    const float inv0 = 1.0f / l0, inv1 = 1.0f / l1;
#pragma unroll
    for (int nj = 0; nj < 8; nj++) {
        const int d = nj * 8 + 2 * t;
        *(__half2*)&Ag[(size_t)(q0 + qrow) * Dn + d] =
            __floats2half2_rn(o[nj][0] * inv0, o[nj][1] * inv0);
        *(__half2*)&Ag[(size_t)(q0 + qrow + 8) * Dn + d] =
            __floats2half2_rn(o[nj][2] * inv1, o[nj][3] * inv1);
    }
}

// ---------------------------------------------------------------------------
extern "C" void kernel_launch(void* const* d_in, const int* in_sizes, int n_in,
                              void* d_out, int out_size)
{
    const float* x  = (const float*)d_in[0];
    const float* Wq = (const float*)d_in[1];
    const float* Wk = (const float*)d_in[2];
    const float* Wv = (const float*)d_in[3];
    const float* Wo = (const float*)d_in[4];
    const float* bo = (const float*)d_in[5];
    float* out = (float*)d_out;

    cudaFuncSetAttribute(qkv_h_kernel,
                         cudaFuncAttributeMaxDynamicSharedMemorySize, GEMM_SMEM);
    cudaFuncSetAttribute(oproj_h_kernel,
                         cudaFuncAttributeMaxDynamicSharedMemorySize, GEMM_SMEM);

    xconv_kernel<<<(Bn * Tn * Cn) / 1024, 256>>>(x);
    wtrans_kernel<<<dim3(Cn / 32, Cn / 32, 4), dim3(32, 8)>>>(Wq, Wk, Wv, Wo);

    qkv_h_kernel<<<dim3(Cn / 128, (Bn * Tn) / 128, 3), 256, GEMM_SMEM>>>();

    flash_h_kernel<<<dim3(Tn / 64, Hn, Bn), 128>>>();

    oproj_h_kernel<<<dim3(Cn / 128, (Bn * Tn) / 128), 256, GEMM_SMEM>>>(bo, out);
}

// round 13
// speedup vs baseline: 1.3396x; 1.0559x over previous
#include <cuda_runtime.h>
#include <cuda_fp16.h>
#include <cstdint>

#define Bn 4
#define Tn 2048
#define Cn 1024
#define Hn 16
#define Dn 64

// Inter-kernel tensors in half, [B,H,T,D]
__device__ __half g_Q[Bn * Hn * Tn * Dn];
__device__ __half g_K[Bn * Hn * Tn * Dn];
__device__ __half g_V[Bn * Hn * Tn * Dn];
__device__ __half g_A[Bn * Hn * Tn * Dn];
__device__ __half g_Xh[Bn * Tn * Cn];         // half(x), row-major [B*T][C]
__device__ __half g_Wt[4][Cn * Cn];           // Wt[z][n][k] = half(W_z[k][n])

__device__ __forceinline__ unsigned h2u(float a, float b) {
    __half2 h = __floats2half2_rn(a, b);
    return *(unsigned*)&h;
}
__device__ __forceinline__ unsigned h2exp2(unsigned x) {
    unsigned r;
    asm("ex2.approx.f16x2 %0, %1;" : "=r"(r) : "r"(x));
    return r;
}
__device__ __forceinline__ void mma_f16(float* c, const unsigned* a, const unsigned* b) {
    asm volatile(
        "mma.sync.aligned.m16n8k16.row.col.f32.f16.f16.f32 "
        "{%0,%1,%2,%3}, {%4,%5,%6,%7}, {%8,%9}, {%0,%1,%2,%3};\n"
        : "+f"(c[0]), "+f"(c[1]), "+f"(c[2]), "+f"(c[3])
        : "r"(a[0]), "r"(a[1]), "r"(a[2]), "r"(a[3]), "r"(b[0]), "r"(b[1]));
}
__device__ __forceinline__ void ldsm_x4(unsigned* r, uint32_t addr) {
    asm volatile(
        "ldmatrix.sync.aligned.m8n8.x4.shared.b16 {%0,%1,%2,%3}, [%4];"
        : "=r"(r[0]), "=r"(r[1]), "=r"(r[2]), "=r"(r[3]) : "r"(addr));
}
__device__ __forceinline__ void ldsm_x4_t(unsigned* r, uint32_t addr) {
    asm volatile(
        "ldmatrix.sync.aligned.m8n8.x4.trans.shared.b16 {%0,%1,%2,%3}, [%4];"
        : "=r"(r[0]), "=r"(r[1]), "=r"(r[2]), "=r"(r[3]) : "r"(addr));
}
__device__ __forceinline__ void cp16(uint32_t dst, const void* src) {
    asm volatile("cp.async.cg.shared.global [%0], [%1], 16;" :: "r"(dst), "l"(src) : "memory");
}

// ---------------------------------------------------------------------------
// One-shot input conversion: g_Xh = half(x)
// ---------------------------------------------------------------------------
__global__ __launch_bounds__(256) void xconv_kernel(const float* __restrict__ X)
{
    const int i = (blockIdx.x * 256 + threadIdx.x) * 4;
    float4 v = *(const float4*)&X[i];
    __half2 h0 = __floats2half2_rn(v.x, v.y);
    __half2 h1 = __floats2half2_rn(v.z, v.w);
    *(uint2*)&g_Xh[i] = make_uint2(*(unsigned*)&h0, *(unsigned*)&h1);
}

// ---------------------------------------------------------------------------
// One-shot weight transpose: g_Wt[z][n][k] = half(W_z[k][n])
// ---------------------------------------------------------------------------
__global__ __launch_bounds__(256) void wtrans_kernel(
    const float* __restrict__ Wq, const float* __restrict__ Wk,
    const float* __restrict__ Wv, const float* __restrict__ Wo)
{
    __shared__ float tile[32][33];
    const int z = blockIdx.z;
    const float* __restrict__ W = (z == 0) ? Wq : (z == 1) ? Wk : (z == 2) ? Wv : Wo;
    const int x0 = blockIdx.x << 5, y0 = blockIdx.y << 5;
    const int tx = threadIdx.x, ty = threadIdx.y;
#pragma unroll
    for (int j = 0; j < 32; j += 8)
        tile[ty + j][tx] = W[(size_t)(y0 + ty + j) * Cn + x0 + tx];
    __syncthreads();
#pragma unroll
    for (int j = 0; j < 32; j += 8)
        g_Wt[z][(size_t)(x0 + ty + j) * Cn + y0 + tx] = __float2half_rn(tile[tx][ty + j]);
}

// ---------------------------------------------------------------------------
// fp16 GEMM: block 128x128, BK=32, 8 warps (warp 64x32), 3-stage cp.async.
// ---------------------------------------------------------------------------
#define QP 40
#define NST 3
#define STG_H (128 * QP)
#define GEMM_SMEM (2 * NST * STG_H * 2)

#define GEMM_COMPUTE()                                                          \
    do {                                                                        \
        const uint32_t so = 2u * (unsigned)(cur * STG_H);                       \
        _Pragma("unroll")                                                       \
        for (int ks = 0; ks < 2; ks++) {                                        \
            const int kk = ks << 4;                                             \
            unsigned bf[2][4];                                                  \
            _Pragma("unroll")                                                   \
            for (int p = 0; p < 2; p++) {                                       \
                const unsigned rn = warpn * 32 + p * 16 + b_lr;                 \
                ldsm_x4(bf[p], bBase + so + 2u * (rn * QP + kk + b_lc));        \
            }                                                                   \
            _Pragma("unroll")                                                   \
            for (int mi = 0; mi < 4; mi++) {                                    \
                unsigned a[4];                                                  \
                const unsigned rm = warpm * 64 + mi * 16 + a_lr;                \
                ldsm_x4(a, aBase + so + 2u * (rm * QP + kk + a_lc));            \
                _Pragma("unroll")                                               \
                for (int nj = 0; nj < 4; nj++) {                                \
                    unsigned bb[2] = {bf[nj >> 1][(nj & 1) * 2],                \
                                      bf[nj >> 1][(nj & 1) * 2 + 1]};           \
                    mma_f16(c[mi][nj], a, bb);                                  \
                }                                                               \
            }                                                                   \
        }                                                                       \
    } while (0)

__global__ __launch_bounds__(256, 2) void qkv_h_kernel()
{
    extern __shared__ __align__(16) __half smg[];
    __half* As = smg;
    __half* Bs = smg + NST * STG_H;

    const int z = blockIdx.z;
    const __half* __restrict__ Wt = g_Wt[z];
    __half* __restrict__ Y = (z == 0) ? g_Q : (z == 1) ? g_K : g_V;
    // fold softmax scale (1/8) and log2e into Q so flash works in log2 domain
    const float yscale = (z == 0) ? 0.1803368801f : 1.0f;

    const int tid = threadIdx.x;
    const int lane = tid & 31, wid = tid >> 5;
    const int g = lane >> 2, t = lane & 3;
    const int warpm = wid >> 2, warpn = wid & 3;
    const int m0 = blockIdx.y << 7, n0 = blockIdx.x << 7;

    const int row = tid >> 1, e = tid & 1;
    const __half* Asrc = &g_Xh[(size_t)(m0 + row) * Cn + e * 16];
    const __half* Bsrc = &Wt[(size_t)(n0 + row) * Cn + e * 16];
    const uint32_t aSm = (uint32_t)__cvta_generic_to_shared(&As[row * QP + e * 16]);
    const uint32_t bSm = (uint32_t)__cvta_generic_to_shared(&Bs[row * QP + e * 16]);

    auto stage = [&](int stg, int k0) {
        const uint32_t ao = aSm + 2u * (unsigned)(stg * STG_H);
        cp16(ao, Asrc + k0);
        cp16(ao + 16, Asrc + k0 + 8);
        const uint32_t bo2 = bSm + 2u * (unsigned)(stg * STG_H);
        cp16(bo2, Bsrc + k0);
        cp16(bo2 + 16, Bsrc + k0 + 8);
        asm volatile("cp.async.commit_group;" ::: "memory");
    };

    float c[4][4][4] = {};
    stage(0, 0);
    stage(1, 32);

    const unsigned a_lr = (lane & 7) + (((lane >> 3) & 1) << 3);
    const unsigned a_lc = ((lane >> 4) & 1) << 3;
    const unsigned b_lr = (((lane >> 4) & 1) << 3) + (lane & 7);
    const unsigned b_lc = ((lane >> 3) & 1) << 3;
    const uint32_t aBase = (uint32_t)__cvta_generic_to_shared(As);
    const uint32_t bBase = (uint32_t)__cvta_generic_to_shared(Bs);

    for (int it = 0; it < Cn / 32; ++it) {
        const int cur = it % NST;
        if (it + 2 < Cn / 32)
            asm volatile("cp.async.wait_group 1;" ::: "memory");
        else
            asm volatile("cp.async.wait_group 0;" ::: "memory");
        __syncthreads();
        GEMM_COMPUTE();
        if (it + 2 < Cn / 32) stage((it + 2) % NST, (it + 2) * 32);
        __syncthreads();
    }

#pragma unroll
    for (int mi = 0; mi < 4; mi++) {
#pragma unroll
        for (int r = 0; r < 2; r++) {
            const int mrow = m0 + warpm * 64 + mi * 16 + g + 8 * r;
            const int b_ = mrow >> 11, t_ = mrow & (Tn - 1);
#pragma unroll
            for (int nj = 0; nj < 4; nj++) {
                const int n = n0 + warpn * 32 + nj * 8 + 2 * t;
                const int h = n >> 6, d = n & 63;
                __half2 hv = __floats2half2_rn(c[mi][nj][2 * r] * yscale,
                                               c[mi][nj][2 * r + 1] * yscale);
                *(__half2*)&Y[(size_t)((b_ * Hn + h) * Tn + t_) * Dn + d] = hv;
            }
        }
    }
}

__global__ __launch_bounds__(256, 2) void oproj_h_kernel(
    const float* __restrict__ bo, float* __restrict__ out)
{
    extern __shared__ __align__(16) __half smg[];
    __half* As = smg;
    __half* Bs = smg + NST * STG_H;
    const __half* __restrict__ Wt = g_Wt[3];

    const int tid = threadIdx.x;
    const int lane = tid & 31, wid = tid >> 5;
    const int g = lane >> 2, t = lane & 3;
    const int warpm = wid >> 2, warpn = wid & 3;
    const int m0 = blockIdx.y << 7, n0 = blockIdx.x << 7;

    const int row = tid >> 1, e = tid & 1;
    const int m = m0 + row;
    const int mb = m >> 11, mt = m & (Tn - 1);
    const __half* aRowBase = &g_A[((size_t)(mb * Hn) * Tn + mt) * Dn + e * 16];
    const __half* Bsrc = &Wt[(size_t)(n0 + row) * Cn + e * 16];
    const uint32_t aSm = (uint32_t)__cvta_generic_to_shared(&As[row * QP + e * 16]);
    const uint32_t bSm = (uint32_t)__cvta_generic_to_shared(&Bs[row * QP + e * 16]);

    auto stage = [&](int stg, int k0) {
        const __half* as = aRowBase + (size_t)(k0 >> 6) * Tn * Dn + (k0 & 63);
        const uint32_t ao = aSm + 2u * (unsigned)(stg * STG_H);
        cp16(ao, as);
        cp16(ao + 16, as + 8);
        const uint32_t bo2 = bSm + 2u * (unsigned)(stg * STG_H);
        cp16(bo2, Bsrc + k0);
        cp16(bo2 + 16, Bsrc + k0 + 8);
        asm volatile("cp.async.commit_group;" ::: "memory");
    };

    float c[4][4][4] = {};
    stage(0, 0);
    stage(1, 32);

    const unsigned a_lr = (lane & 7) + (((lane >> 3) & 1) << 3);
    const unsigned a_lc = ((lane >> 4) & 1) << 3;
    const unsigned b_lr = (((lane >> 4) & 1) << 3) + (lane & 7);
    const unsigned b_lc = ((lane >> 3) & 1) << 3;
    const uint32_t aBase = (uint32_t)__cvta_generic_to_shared(As);
    const uint32_t bBase = (uint32_t)__cvta_generic_to_shared(Bs);

    for (int it = 0; it < Cn / 32; ++it) {
        const int cur = it % NST;
        if (it + 2 < Cn / 32)
            asm volatile("cp.async.wait_group 1;" ::: "memory");
        else
            asm volatile("cp.async.wait_group 0;" ::: "memory");
        __syncthreads();
        GEMM_COMPUTE();
        if (it + 2 < Cn / 32) stage((it + 2) % NST, (it + 2) * 32);
        __syncthreads();
    }

#pragma unroll
    for (int mi = 0; mi < 4; mi++) {
#pragma unroll
        for (int r = 0; r < 2; r++) {
            const int mrow = m0 + warpm * 64 + mi * 16 + g + 8 * r;
#pragma unroll
            for (int nj = 0; nj < 4; nj++) {
                const int n = n0 + warpn * 32 + nj * 8 + 2 * t;
                float2 bias = *(const float2*)&bo[n];
                float2 v = {c[mi][nj][2 * r] + bias.x, c[mi][nj][2 * r + 1] + bias.y};
                *(float2*)&out[(size_t)mrow * Cn + n] = v;
            }
        }
    }
}

// ---------------------------------------------------------------------------
// Flash attention fp16: Br=Bc=64, 4 warps, Q frags in registers,
// double-buffered cp.async K/V staging, P in registers, log2-domain softmax
// with ex2.approx.f16x2, row sums via ones-mma (no sum shuffles).
// ---------------------------------------------------------------------------
#define FP 72
#define KV_STG (64 * FP)   // halves per K (or V) buffer

__global__ __launch_bounds__(128, 4) void flash_h_kernel()
{
    __shared__ __half Ks[2][64][FP];
    __shared__ __half Vs[2][64][FP];
    __shared__ __half Ps[64][FP];   // Q staging only

    const int qb = blockIdx.x;
    const int h = blockIdx.y, b = blockIdx.z;
    const int tid = threadIdx.x;
    const int lane = tid & 31, wid = tid >> 5;
    const int g = lane >> 2, t = lane & 3;
    const int q0 = qb << 6;
    const int qrow = (wid << 4) + g;

    const size_t base = (size_t)((b * Hn + h) * Tn) * Dn;
    const __half* __restrict__ Qg = g_Q + base;
    const __half* __restrict__ Kg = g_K + base;
    const __half* __restrict__ Vg = g_V + base;

    const int srow = tid >> 1, se = tid & 1;
    const uint32_t ksBase = (uint32_t)__cvta_generic_to_shared(&Ks[0][0][0]);
    const uint32_t vsBase = (uint32_t)__cvta_generic_to_shared(&Vs[0][0][0]);
    const uint32_t psBase = (uint32_t)__cvta_generic_to_shared(&Ps[0][0]);

    const uint32_t kDst = ksBase + 2u * (srow * FP + se * 32);
    const uint32_t vDst = vsBase + 2u * (srow * FP + se * 32);
    auto stageKV = [&](int buf, int k0) {
        const __half* ks = &Kg[(size_t)(k0 + srow) * Dn + se * 32];
        const __half* vs = &Vg[(size_t)(k0 + srow) * Dn + se * 32];
        const uint32_t off = 2u * (unsigned)(buf * KV_STG);
#pragma unroll
        for (int j = 0; j < 4; j++) {
            cp16(kDst + off + j * 16, ks + j * 8);
            cp16(vDst + off + j * 16, vs + j * 8);
        }
        asm volatile("cp.async.commit_group;" ::: "memory");
    };

    // stage Q into Ps, lift A-fragments to registers
    {
        const uint4* qp = (const uint4*)&Qg[(size_t)(q0 + srow) * Dn + se * 32];
#pragma unroll
        for (int j = 0; j < 4; j++)
            *(uint4*)&Ps[srow][se * 32 + j * 8] = qp[j];
    }
    stageKV(0, 0);
    if (qb > 0) stageKV(1, 64);
    __syncthreads();

    const unsigned a_lr = (lane & 7) + (((lane >> 3) & 1) << 3);
    const unsigned a_lc = ((lane >> 4) & 1) << 3;

    unsigned qa[4][4];
#pragma unroll
    for (int ks = 0; ks < 4; ks++)
        ldsm_x4(qa[ks], psBase + 2u * ((wid * 16 + a_lr) * FP + ks * 16 + a_lc));

    const unsigned ones2[2] = {0x3C003C00u, 0x3C003C00u};  // {1h,1h},{1h,1h}

    float o[8][4] = {};
    float lac[4] = {0.f, 0.f, 0.f, 0.f};   // ones-mma accumulator: c0/c1 row qrow, c2/c3 row qrow+8
    float mv0 = -1e30f, mv1 = -1e30f;

    for (int kb = 0; kb <= qb; kb++) {
        if (kb < qb)
            asm volatile("cp.async.wait_group 1;" ::: "memory");
        else
            asm volatile("cp.async.wait_group 0;" ::: "memory");
        __syncthreads();

        const uint32_t so = 2u * (unsigned)((kb & 1) * KV_STG);

        // ---- S = Q @ K^T (log2-domain: scale folded into Q) ----
        float s[8][4] = {};
#pragma unroll
        for (int nj = 0; nj < 8; nj++) {
            unsigned bf[8];
            const uint32_t ad = ksBase + so +
                2u * ((nj * 8 + (lane & 7)) * FP + (lane >> 3) * 8);
            ldsm_x4(bf, ad);
            ldsm_x4(bf + 4, ad + 64);
#pragma unroll
            for (int ks = 0; ks < 4; ks++) {
                unsigned bb[2] = {bf[2 * ks], bf[2 * ks + 1]};
                mma_f16(s[nj], qa[ks], bb);
            }
        }

        // ---- causal mask ----
        const bool diag = (kb == qb);
        if (diag) {
#pragma unroll
            for (int nj = 0; nj < 8; nj++) {
                const int col0 = nj * 8 + 2 * t, col1 = col0 + 1;
                if (col0 > qrow) s[nj][0] = -1e30f;
                if (col1 > qrow) s[nj][1] = -1e30f;
                if (col0 > qrow + 8) s[nj][2] = -1e30f;
                if (col1 > qrow + 8) s[nj][3] = -1e30f;
            }
        }

        // ---- row max (quad shuffles) ----
        float mt0 = -1e30f, mt1 = -1e30f;
#pragma unroll
        for (int nj = 0; nj < 8; nj++) {
            mt0 = fmaxf(mt0, fmaxf(s[nj][0], s[nj][1]));
            mt1 = fmaxf(mt1, fmaxf(s[nj][2], s[nj][3]));
        }
        mt0 = fmaxf(mt0, __shfl_xor_sync(0xffffffffu, mt0, 1));
        mt0 = fmaxf(mt0, __shfl_xor_sync(0xffffffffu, mt0, 2));
        mt1 = fmaxf(mt1, __shfl_xor_sync(0xffffffffu, mt1, 1));
        mt1 = fmaxf(mt1, __shfl_xor_sync(0xffffffffu, mt1, 2));

        const float mn0 = fmaxf(mv0, mt0);
        const float mn1 = fmaxf(mv1, mt1);

        // ---- P = exp2(S - m) via f16x2, packed directly into A-fragments ----
        unsigned pa[4][4];
#pragma unroll
        for (int nj = 0; nj < 8; nj++) {
            unsigned ph0 = h2exp2(h2u(s[nj][0] - mn0, s[nj][1] - mn0));
            unsigned ph1 = h2exp2(h2u(s[nj][2] - mn1, s[nj][3] - mn1));
            pa[nj >> 1][(nj & 1) * 2] = ph0;
            pa[nj >> 1][(nj & 1) * 2 + 1] = ph1;
        }

        // ---- rescale O and l; accumulate row sums via ones-mma ----
        const float cf0 = exp2f(mv0 - mn0);
        const float cf1 = exp2f(mv1 - mn1);
        mv0 = mn0;
        mv1 = mn1;
#pragma unroll
        for (int nj = 0; nj < 8; nj++) {
            o[nj][0] *= cf0; o[nj][1] *= cf0;
            o[nj][2] *= cf1; o[nj][3] *= cf1;
        }
        lac[0] *= cf0; lac[1] *= cf0;
        lac[2] *= cf1; lac[3] *= cf1;
#pragma unroll
        for (int ks = 0; ks < 4; ks++)
            mma_f16(lac, pa[ks], ones2);

        // ---- O += P @ V ----
#pragma unroll
        for (int nj = 0; nj < 8; nj++) {
            unsigned vf[8];
            ldsm_x4_t(vf, vsBase + so + 2u * (lane * FP + nj * 8));
            ldsm_x4_t(vf + 4, vsBase + so + 2u * ((32 + lane) * FP + nj * 8));
#pragma unroll
            for (int ks = 0; ks < 4; ks++) {
                unsigned bb[2] = {vf[2 * ks], vf[2 * ks + 1]};
                mma_f16(o[nj], pa[ks], bb);
            }
        }
        __syncthreads();
        if (kb + 2 <= qb) stageKV(kb & 1, (kb + 2) << 6);
    }

    // ---- normalize + write g_A (half) ----
    __half* __restrict__ Ag = g_A + base;
    const float inv0 = 1.0f / lac[0], inv1 = 1.0f / lac[2];
#pragma unroll
    for (int nj = 0; nj < 8; nj++) {
        const int d = nj * 8 + 2 * t;
        *(__half2*)&Ag[(size_t)(q0 + qrow) * Dn + d] =
            __floats2half2_rn(o[nj][0] * inv0, o[nj][1] * inv0);
        *(__half2*)&Ag[(size_t)(q0 + qrow + 8) * Dn + d] =
            __floats2half2_rn(o[nj][2] * inv1, o[nj][3] * inv1);
    }
}

// ---------------------------------------------------------------------------
extern "C" void kernel_launch(void* const* d_in, const int* in_sizes, int n_in,
                              void* d_out, int out_size)
{
    const float* x  = (const float*)d_in[0];
    const float* Wq = (const float*)d_in[1];
    const float* Wk = (const float*)d_in[2];
    const float* Wv = (const float*)d_in[3];
    const float* Wo = (const float*)d_in[4];
    const float* bo = (const float*)d_in[5];
    float* out = (float*)d_out;

    cudaFuncSetAttribute(qkv_h_kernel,
                         cudaFuncAttributeMaxDynamicSharedMemorySize, GEMM_SMEM);
    cudaFuncSetAttribute(oproj_h_kernel,
                         cudaFuncAttributeMaxDynamicSharedMemorySize, GEMM_SMEM);

    xconv_kernel<<<(Bn * Tn * Cn) / 1024, 256>>>(x);
    wtrans_kernel<<<dim3(Cn / 32, Cn / 32, 4), dim3(32, 8)>>>(Wq, Wk, Wv, Wo);

    qkv_h_kernel<<<dim3(Cn / 128, (Bn * Tn) / 128, 3), 256, GEMM_SMEM>>>();

    flash_h_kernel<<<dim3(Tn / 64, Hn, Bn), 128>>>();

    oproj_h_kernel<<<dim3(Cn / 128, (Bn * Tn) / 128), 256, GEMM_SMEM>>>(bo, out);
}

// round 14
// speedup vs baseline: 1.4164x; 1.0573x over previous
#include <cuda_runtime.h>
#include <cuda_fp16.h>
#include <cstdint>

#define Bn 4
#define Tn 2048
#define Cn 1024
#define Hn 16
#define Dn 64

// Inter-kernel tensors in half, [B,H,T,D]
__device__ __half g_Q[Bn * Hn * Tn * Dn];
__device__ __half g_K[Bn * Hn * Tn * Dn];
__device__ __half g_V[Bn * Hn * Tn * Dn];
__device__ __half g_A[Bn * Hn * Tn * Dn];
__device__ __half g_Xh[Bn * Tn * Cn];         // half(x), row-major [B*T][C]
__device__ __half g_Wt[4][Cn * Cn];           // Wt[z][n][k] = half(W_z[k][n])

__device__ __forceinline__ unsigned h2u(float a, float b) {
    __half2 h = __floats2half2_rn(a, b);
    return *(unsigned*)&h;
}
__device__ __forceinline__ unsigned h2exp2(unsigned x) {
    unsigned r;
    asm("ex2.approx.f16x2 %0, %1;" : "=r"(r) : "r"(x));
    return r;
}
__device__ __forceinline__ void mma_f16(float* c, const unsigned* a, const unsigned* b) {
    asm volatile(
        "mma.sync.aligned.m16n8k16.row.col.f32.f16.f16.f32 "
        "{%0,%1,%2,%3}, {%4,%5,%6,%7}, {%8,%9}, {%0,%1,%2,%3};\n"
        : "+f"(c[0]), "+f"(c[1]), "+f"(c[2]), "+f"(c[3])
        : "r"(a[0]), "r"(a[1]), "r"(a[2]), "r"(a[3]), "r"(b[0]), "r"(b[1]));
}
__device__ __forceinline__ void ldsm_x4(unsigned* r, uint32_t addr) {
    asm volatile(
        "ldmatrix.sync.aligned.m8n8.x4.shared.b16 {%0,%1,%2,%3}, [%4];"
        : "=r"(r[0]), "=r"(r[1]), "=r"(r[2]), "=r"(r[3]) : "r"(addr));
}
__device__ __forceinline__ void ldsm_x4_t(unsigned* r, uint32_t addr) {
    asm volatile(
        "ldmatrix.sync.aligned.m8n8.x4.trans.shared.b16 {%0,%1,%2,%3}, [%4];"
        : "=r"(r[0]), "=r"(r[1]), "=r"(r[2]), "=r"(r[3]) : "r"(addr));
}
__device__ __forceinline__ void cp16(uint32_t dst, const void* src) {
    asm volatile("cp.async.cg.shared.global [%0], [%1], 16;" :: "r"(dst), "l"(src) : "memory");
}

// ---------------------------------------------------------------------------
// One-shot input conversion: g_Xh = half(x)
// ---------------------------------------------------------------------------
__global__ __launch_bounds__(256) void xconv_kernel(const float* __restrict__ X)
{
    const int i = (blockIdx.x * 256 + threadIdx.x) * 4;
    float4 v = *(const float4*)&X[i];
    __half2 h0 = __floats2half2_rn(v.x, v.y);
    __half2 h1 = __floats2half2_rn(v.z, v.w);
    *(uint2*)&g_Xh[i] = make_uint2(*(unsigned*)&h0, *(unsigned*)&h1);
}

// ---------------------------------------------------------------------------
// One-shot weight transpose: g_Wt[z][n][k] = half(W_z[k][n])
// ---------------------------------------------------------------------------
__global__ __launch_bounds__(256) void wtrans_kernel(
    const float* __restrict__ Wq, const float* __restrict__ Wk,
    const float* __restrict__ Wv, const float* __restrict__ Wo)
{
    __shared__ float tile[32][33];
    const int z = blockIdx.z;
    const float* __restrict__ W = (z == 0) ? Wq : (z == 1) ? Wk : (z == 2) ? Wv : Wo;
    const int x0 = blockIdx.x << 5, y0 = blockIdx.y << 5;
    const int tx = threadIdx.x, ty = threadIdx.y;
#pragma unroll
    for (int j = 0; j < 32; j += 8)
        tile[ty + j][tx] = W[(size_t)(y0 + ty + j) * Cn + x0 + tx];
    __syncthreads();
#pragma unroll
    for (int j = 0; j < 32; j += 8)
        g_Wt[z][(size_t)(x0 + ty + j) * Cn + y0 + tx] = __float2half_rn(tile[tx][ty + j]);
}

// ---------------------------------------------------------------------------
// fp16 GEMM: block 128x128, BK=32, 8 warps (warp 64x32), 3-stage cp.async.
// Single barrier per iteration (3-stage ring makes the trailing sync redundant).
// ---------------------------------------------------------------------------
#define QP 40
#define NST 3
#define STG_H (128 * QP)
#define GEMM_SMEM (2 * NST * STG_H * 2)

#define GEMM_COMPUTE()                                                          \
    do {                                                                        \
        const uint32_t so = 2u * (unsigned)(cur * STG_H);                       \
        _Pragma("unroll")                                                       \
        for (int ks = 0; ks < 2; ks++) {                                        \
            const int kk = ks << 4;                                             \
            unsigned bf[2][4];                                                  \
            _Pragma("unroll")                                                   \
            for (int p = 0; p < 2; p++) {                                       \
                const unsigned rn = warpn * 32 + p * 16 + b_lr;                 \
                ldsm_x4(bf[p], bBase + so + 2u * (rn * QP + kk + b_lc));        \
            }                                                                   \
            _Pragma("unroll")                                                   \
            for (int mi = 0; mi < 4; mi++) {                                    \
                unsigned a[4];                                                  \
                const unsigned rm = warpm * 64 + mi * 16 + a_lr;                \
                ldsm_x4(a, aBase + so + 2u * (rm * QP + kk + a_lc));            \
                _Pragma("unroll")                                               \
                for (int nj = 0; nj < 4; nj++) {                                \
                    unsigned bb[2] = {bf[nj >> 1][(nj & 1) * 2],                \
                                      bf[nj >> 1][(nj & 1) * 2 + 1]};           \
                    mma_f16(c[mi][nj], a, bb);                                  \
                }                                                               \
            }                                                                   \
        }                                                                       \
    } while (0)

__global__ __launch_bounds__(256, 2) void qkv_h_kernel()
{
    extern __shared__ __align__(16) __half smg[];
    __half* As = smg;
    __half* Bs = smg + NST * STG_H;

    const int z = blockIdx.z;
    const __half* __restrict__ Wt = g_Wt[z];
    __half* __restrict__ Y = (z == 0) ? g_Q : (z == 1) ? g_K : g_V;
    // fold softmax scale (1/8) and log2e into Q so flash works in log2 domain
    const float yscale = (z == 0) ? 0.1803368801f : 1.0f;

    const int tid = threadIdx.x;
    const int lane = tid & 31, wid = tid >> 5;
    const int g = lane >> 2, t = lane & 3;
    const int warpm = wid >> 2, warpn = wid & 3;
    const int m0 = blockIdx.y << 7, n0 = blockIdx.x << 7;

    const int row = tid >> 1, e = tid & 1;
    const __half* Asrc = &g_Xh[(size_t)(m0 + row) * Cn + e * 16];
    const __half* Bsrc = &Wt[(size_t)(n0 + row) * Cn + e * 16];
    const uint32_t aSm = (uint32_t)__cvta_generic_to_shared(&As[row * QP + e * 16]);
    const uint32_t bSm = (uint32_t)__cvta_generic_to_shared(&Bs[row * QP + e * 16]);

    auto stage = [&](int stg, int k0) {
        const uint32_t ao = aSm + 2u * (unsigned)(stg * STG_H);
        cp16(ao, Asrc + k0);
        cp16(ao + 16, Asrc + k0 + 8);
        const uint32_t bo2 = bSm + 2u * (unsigned)(stg * STG_H);
        cp16(bo2, Bsrc + k0);
        cp16(bo2 + 16, Bsrc + k0 + 8);
        asm volatile("cp.async.commit_group;" ::: "memory");
    };

    float c[4][4][4] = {};
    stage(0, 0);
    stage(1, 32);

    const unsigned a_lr = (lane & 7) + (((lane >> 3) & 1) << 3);
    const unsigned a_lc = ((lane >> 4) & 1) << 3;
    const unsigned b_lr = (((lane >> 4) & 1) << 3) + (lane & 7);
    const unsigned b_lc = ((lane >> 3) & 1) << 3;
    const uint32_t aBase = (uint32_t)__cvta_generic_to_shared(As);
    const uint32_t bBase = (uint32_t)__cvta_generic_to_shared(Bs);

    for (int it = 0; it < Cn / 32; ++it) {
        const int cur = it % NST;
        if (it + 2 < Cn / 32)
            asm volatile("cp.async.wait_group 1;" ::: "memory");
        else
            asm volatile("cp.async.wait_group 0;" ::: "memory");
        __syncthreads();
        GEMM_COMPUTE();
        if (it + 2 < Cn / 32) stage((it + 2) % NST, (it + 2) * 32);
    }

#pragma unroll
    for (int mi = 0; mi < 4; mi++) {
#pragma unroll
        for (int r = 0; r < 2; r++) {
            const int mrow = m0 + warpm * 64 + mi * 16 + g + 8 * r;
            const int b_ = mrow >> 11, t_ = mrow & (Tn - 1);
#pragma unroll
            for (int nj = 0; nj < 4; nj++) {
                const int n = n0 + warpn * 32 + nj * 8 + 2 * t;
                const int h = n >> 6, d = n & 63;
                __half2 hv = __floats2half2_rn(c[mi][nj][2 * r] * yscale,
                                               c[mi][nj][2 * r + 1] * yscale);
                *(__half2*)&Y[(size_t)((b_ * Hn + h) * Tn + t_) * Dn + d] = hv;
            }
        }
    }
}

__global__ __launch_bounds__(256, 2) void oproj_h_kernel(
    const float* __restrict__ bo, float* __restrict__ out)
{
    extern __shared__ __align__(16) __half smg[];
    __half* As = smg;
    __half* Bs = smg + NST * STG_H;
    const __half* __restrict__ Wt = g_Wt[3];

    const int tid = threadIdx.x;
    const int lane = tid & 31, wid = tid >> 5;
    const int g = lane >> 2, t = lane & 3;
    const int warpm = wid >> 2, warpn = wid & 3;
    const int m0 = blockIdx.y << 7, n0 = blockIdx.x << 7;

    const int row = tid >> 1, e = tid & 1;
    const int m = m0 + row;
    const int mb = m >> 11, mt = m & (Tn - 1);
    const __half* aRowBase = &g_A[((size_t)(mb * Hn) * Tn + mt) * Dn + e * 16];
    const __half* Bsrc = &Wt[(size_t)(n0 + row) * Cn + e * 16];
    const uint32_t aSm = (uint32_t)__cvta_generic_to_shared(&As[row * QP + e * 16]);
    const uint32_t bSm = (uint32_t)__cvta_generic_to_shared(&Bs[row * QP + e * 16]);

    auto stage = [&](int stg, int k0) {
        const __half* as = aRowBase + (size_t)(k0 >> 6) * Tn * Dn + (k0 & 63);
        const uint32_t ao = aSm + 2u * (unsigned)(stg * STG_H);
        cp16(ao, as);
        cp16(ao + 16, as + 8);
        const uint32_t bo2 = bSm + 2u * (unsigned)(stg * STG_H);
        cp16(bo2, Bsrc + k0);
        cp16(bo2 + 16, Bsrc + k0 + 8);
        asm volatile("cp.async.commit_group;" ::: "memory");
    };

    float c[4][4][4] = {};
    stage(0, 0);
    stage(1, 32);

    const unsigned a_lr = (lane & 7) + (((lane >> 3) & 1) << 3);
    const unsigned a_lc = ((lane >> 4) & 1) << 3;
    const unsigned b_lr = (((lane >> 4) & 1) << 3) + (lane & 7);
    const unsigned b_lc = ((lane >> 3) & 1) << 3;
    const uint32_t aBase = (uint32_t)__cvta_generic_to_shared(As);
    const uint32_t bBase = (uint32_t)__cvta_generic_to_shared(Bs);

    for (int it = 0; it < Cn / 32; ++it) {
        const int cur = it % NST;
        if (it + 2 < Cn / 32)
            asm volatile("cp.async.wait_group 1;" ::: "memory");
        else
            asm volatile("cp.async.wait_group 0;" ::: "memory");
        __syncthreads();
        GEMM_COMPUTE();
        if (it + 2 < Cn / 32) stage((it + 2) % NST, (it + 2) * 32);
    }

#pragma unroll
    for (int mi = 0; mi < 4; mi++) {
#pragma unroll
        for (int r = 0; r < 2; r++) {
            const int mrow = m0 + warpm * 64 + mi * 16 + g + 8 * r;
#pragma unroll
            for (int nj = 0; nj < 4; nj++) {
                const int n = n0 + warpn * 32 + nj * 8 + 2 * t;
                float2 bias = *(const float2*)&bo[n];
                float2 v = {c[mi][nj][2 * r] + bias.x, c[mi][nj][2 * r + 1] + bias.y};
                *(float2*)&out[(size_t)mrow * Cn + n] = v;
            }
        }
    }
}

// ---------------------------------------------------------------------------
// Flash attention fp16: Br=Bc=64, 4 warps, Q frags in registers, log2-domain
// softmax (ex2.f16x2), ones-mma row sums, double-buffered cp.async K/V with
// SPLIT K/V groups, and next-tile S prefetched before softmax.
// ---------------------------------------------------------------------------
#define FP 72
#define KV_STG (64 * FP)   // halves per K (or V) buffer

__global__ __launch_bounds__(128, 3) void flash_h_kernel()
{
    __shared__ __half Ks[2][64][FP];
    __shared__ __half Vs[2][64][FP];
    __shared__ __half Ps[64][FP];   // Q staging only

    const int qb = blockIdx.x;
    const int h = blockIdx.y, b = blockIdx.z;
    const int tid = threadIdx.x;
    const int lane = tid & 31, wid = tid >> 5;
    const int g = lane >> 2, t = lane & 3;
    const int q0 = qb << 6;
    const int qrow = (wid << 4) + g;

    const size_t base = (size_t)((b * Hn + h) * Tn) * Dn;
    const __half* __restrict__ Qg = g_Q + base;
    const __half* __restrict__ Kg = g_K + base;
    const __half* __restrict__ Vg = g_V + base;

    const int srow = tid >> 1, se = tid & 1;
    const uint32_t ksBase = (uint32_t)__cvta_generic_to_shared(&Ks[0][0][0]);
    const uint32_t vsBase = (uint32_t)__cvta_generic_to_shared(&Vs[0][0][0]);
    const uint32_t psBase = (uint32_t)__cvta_generic_to_shared(&Ps[0][0]);

    const uint32_t kDst = ksBase + 2u * (srow * FP + se * 32);
    const uint32_t vDst = vsBase + 2u * (srow * FP + se * 32);
    auto stageK = [&](int buf, int k0) {
        const __half* ks = &Kg[(size_t)(k0 + srow) * Dn + se * 32];
        const uint32_t off = 2u * (unsigned)(buf * KV_STG);
#pragma unroll
        for (int j = 0; j < 4; j++) cp16(kDst + off + j * 16, ks + j * 8);
        asm volatile("cp.async.commit_group;" ::: "memory");
    };
    auto stageV = [&](int buf, int k0) {
        const __half* vs = &Vg[(size_t)(k0 + srow) * Dn + se * 32];
        const uint32_t off = 2u * (unsigned)(buf * KV_STG);
#pragma unroll
        for (int j = 0; j < 4; j++) cp16(vDst + off + j * 16, vs + j * 8);
        asm volatile("cp.async.commit_group;" ::: "memory");
    };

    // stage Q into Ps, lift A-fragments to registers
    {
        const uint4* qp = (const uint4*)&Qg[(size_t)(q0 + srow) * Dn + se * 32];
#pragma unroll
        for (int j = 0; j < 4; j++)
            *(uint4*)&Ps[srow][se * 32 + j * 8] = qp[j];
    }
    stageK(0, 0);
    stageV(0, 0);
    if (qb > 0) { stageK(1, 64); stageV(1, 64); }
    __syncthreads();

    const unsigned a_lr = (lane & 7) + (((lane >> 3) & 1) << 3);
    const unsigned a_lc = ((lane >> 4) & 1) << 3;

    unsigned qa[4][4];
#pragma unroll
    for (int ks = 0; ks < 4; ks++)
        ldsm_x4(qa[ks], psBase + 2u * ((wid * 16 + a_lr) * FP + ks * 16 + a_lc));

    auto mmaS = [&](float sarr[8][4], uint32_t bufofs) {
#pragma unroll
        for (int nj = 0; nj < 8; nj++) {
            unsigned bf[8];
            const uint32_t ad = ksBase + bufofs +
                2u * ((nj * 8 + (lane & 7)) * FP + (lane >> 3) * 8);
            ldsm_x4(bf, ad);
            ldsm_x4(bf + 4, ad + 64);
#pragma unroll
            for (int ks = 0; ks < 4; ks++) {
                unsigned bb[2] = {bf[2 * ks], bf[2 * ks + 1]};
                mma_f16(sarr[nj], qa[ks], bb);
            }
        }
    };

    const unsigned ones2[2] = {0x3C003C00u, 0x3C003C00u};

    float o[8][4] = {};
    float lac[4] = {0.f, 0.f, 0.f, 0.f};
    float mv0 = -1e30f, mv1 = -1e30f;

    // S for tile 0 (need K0: with 4 groups pending wait_group 3 drains oldest)
    if (qb > 0) asm volatile("cp.async.wait_group 3;" ::: "memory");
    else        asm volatile("cp.async.wait_group 1;" ::: "memory");
    __syncthreads();
    float s[8][4] = {};
    mmaS(s, 0);

    // ---- steady loop: tiles strictly below diagonal (no mask) ----
    for (int kb = 0; kb < qb; kb++) {
        // K_{kb+1} and V_kb guaranteed complete; newest (V_{kb+1}) may remain
        asm volatile("cp.async.wait_group 1;" ::: "memory");
        __syncthreads();

        float s2[8][4] = {};
        mmaS(s2, 2u * (unsigned)(((kb + 1) & 1) * KV_STG));   // prefetch next S
        if (kb + 2 <= qb) stageK(kb & 1, (kb + 2) << 6);

        // softmax on s (overlaps tensor pipe finishing s2)
        float mt0 = -1e30f, mt1 = -1e30f;
#pragma unroll
        for (int nj = 0; nj < 8; nj++) {
            mt0 = fmaxf(mt0, fmaxf(s[nj][0], s[nj][1]));
            mt1 = fmaxf(mt1, fmaxf(s[nj][2], s[nj][3]));
        }
        mt0 = fmaxf(mt0, __shfl_xor_sync(0xffffffffu, mt0, 1));
        mt0 = fmaxf(mt0, __shfl_xor_sync(0xffffffffu, mt0, 2));
        mt1 = fmaxf(mt1, __shfl_xor_sync(0xffffffffu, mt1, 1));
        mt1 = fmaxf(mt1, __shfl_xor_sync(0xffffffffu, mt1, 2));
        const float mn0 = fmaxf(mv0, mt0);
        const float mn1 = fmaxf(mv1, mt1);

        unsigned pa[4][4];
#pragma unroll
        for (int nj = 0; nj < 8; nj++) {
            unsigned ph0 = h2exp2(h2u(s[nj][0] - mn0, s[nj][1] - mn0));
            unsigned ph1 = h2exp2(h2u(s[nj][2] - mn1, s[nj][3] - mn1));
            pa[nj >> 1][(nj & 1) * 2] = ph0;
            pa[nj >> 1][(nj & 1) * 2 + 1] = ph1;
        }

        const float cf0 = exp2f(mv0 - mn0);
        const float cf1 = exp2f(mv1 - mn1);
        mv0 = mn0;
        mv1 = mn1;
#pragma unroll
        for (int nj = 0; nj < 8; nj++) {
            o[nj][0] *= cf0; o[nj][1] *= cf0;
            o[nj][2] *= cf1; o[nj][3] *= cf1;
        }
        lac[0] *= cf0; lac[1] *= cf0;
        lac[2] *= cf1; lac[3] *= cf1;
#pragma unroll
        for (int ks = 0; ks < 4; ks++)
            mma_f16(lac, pa[ks], ones2);

        // O += P @ V_kb
        const uint32_t so = 2u * (unsigned)((kb & 1) * KV_STG);
#pragma unroll
        for (int nj = 0; nj < 8; nj++) {
            unsigned vf[8];
            ldsm_x4_t(vf, vsBase + so + 2u * (lane * FP + nj * 8));
            ldsm_x4_t(vf + 4, vsBase + so + 2u * ((32 + lane) * FP + nj * 8));
#pragma unroll
            for (int ks = 0; ks < 4; ks++) {
                unsigned bb[2] = {vf[2 * ks], vf[2 * ks + 1]};
                mma_f16(o[nj], pa[ks], bb);
            }
        }
        __syncthreads();
        if (kb + 2 <= qb) stageV(kb & 1, (kb + 2) << 6);

#pragma unroll
        for (int nj = 0; nj < 8; nj++) {
            s[nj][0] = s2[nj][0]; s[nj][1] = s2[nj][1];
            s[nj][2] = s2[nj][2]; s[nj][3] = s2[nj][3];
        }
    }

    // ---- final (diagonal) tile kb == qb ----
    {
        asm volatile("cp.async.wait_group 0;" ::: "memory");
        __syncthreads();

#pragma unroll
        for (int nj = 0; nj < 8; nj++) {
            const int col0 = nj * 8 + 2 * t, col1 = col0 + 1;
            if (col0 > qrow) s[nj][0] = -1e30f;
            if (col1 > qrow) s[nj][1] = -1e30f;
            if (col0 > qrow + 8) s[nj][2] = -1e30f;
            if (col1 > qrow + 8) s[nj][3] = -1e30f;
        }

        float mt0 = -1e30f, mt1 = -1e30f;
#pragma unroll
        for (int nj = 0; nj < 8; nj++) {
            mt0 = fmaxf(mt0, fmaxf(s[nj][0], s[nj][1]));
            mt1 = fmaxf(mt1, fmaxf(s[nj][2], s[nj][3]));
        }
        mt0 = fmaxf(mt0, __shfl_xor_sync(0xffffffffu, mt0, 1));
        mt0 = fmaxf(mt0, __shfl_xor_sync(0xffffffffu, mt0, 2));
        mt1 = fmaxf(mt1, __shfl_xor_sync(0xffffffffu, mt1, 1));
        mt1 = fmaxf(mt1, __shfl_xor_sync(0xffffffffu, mt1, 2));
        const float mn0 = fmaxf(mv0, mt0);
        const float mn1 = fmaxf(mv1, mt1);

        unsigned pa[4][4];
#pragma unroll
        for (int nj = 0; nj < 8; nj++) {
            unsigned ph0 = h2exp2(h2u(s[nj][0] - mn0, s[nj][1] - mn0));
            unsigned ph1 = h2exp2(h2u(s[nj][2] - mn1, s[nj][3] - mn1));
            pa[nj >> 1][(nj & 1) * 2] = ph0;
            pa[nj >> 1][(nj & 1) * 2 + 1] = ph1;
        }

        const float cf0 = exp2f(mv0 - mn0);
        const float cf1 = exp2f(mv1 - mn1);
#pragma unroll
        for (int nj = 0; nj < 8; nj++) {
            o[nj][0] *= cf0; o[nj][1] *= cf0;
            o[nj][2] *= cf1; o[nj][3] *= cf1;
        }
        lac[0] *= cf0; lac[1] *= cf0;
        lac[2] *= cf1; lac[3] *= cf1;
#pragma unroll
        for (int ks = 0; ks < 4; ks++)
            mma_f16(lac, pa[ks], ones2);

        const uint32_t so = 2u * (unsigned)((qb & 1) * KV_STG);
#pragma unroll
        for (int nj = 0; nj < 8; nj++) {
            unsigned vf[8];
            ldsm_x4_t(vf, vsBase + so + 2u * (lane * FP + nj * 8));
            ldsm_x4_t(vf + 4, vsBase + so + 2u * ((32 + lane) * FP + nj * 8));
#pragma unroll
            for (int ks = 0; ks < 4; ks++) {
                unsigned bb[2] = {vf[2 * ks], vf[2 * ks + 1]};
                mma_f16(o[nj], pa[ks], bb);
            }
        }
    }

    // ---- normalize + write g_A (half) ----
    __half* __restrict__ Ag = g_A + base;
    const float inv0 = 1.0f / lac[0], inv1 = 1.0f / lac[2];
#pragma unroll
    for (int nj = 0; nj < 8; nj++) {
        const int d = nj * 8 + 2 * t;
        *(__half2*)&Ag[(size_t)(q0 + qrow) * Dn + d] =
            __floats2half2_rn(o[nj][0] * inv0, o[nj][1] * inv0);
        *(__half2*)&Ag[(size_t)(q0 + qrow + 8) * Dn + d] =
            __floats2half2_rn(o[nj][2] * inv1, o[nj][3] * inv1);
    }
}

// ---------------------------------------------------------------------------
extern "C" void kernel_launch(void* const* d_in, const int* in_sizes, int n_in,
                              void* d_out, int out_size)
{
    const float* x  = (const float*)d_in[0];
    const float* Wq = (const float*)d_in[1];
    const float* Wk = (const float*)d_in[2];
    const float* Wv = (const float*)d_in[3];
    const float* Wo = (const float*)d_in[4];
    const float* bo = (const float*)d_in[5];
    float* out = (float*)d_out;

    cudaFuncSetAttribute(qkv_h_kernel,
                         cudaFuncAttributeMaxDynamicSharedMemorySize, GEMM_SMEM);
    cudaFuncSetAttribute(oproj_h_kernel,
                         cudaFuncAttributeMaxDynamicSharedMemorySize, GEMM_SMEM);

    xconv_kernel<<<(Bn * Tn * Cn) / 1024, 256>>>(x);
    wtrans_kernel<<<dim3(Cn / 32, Cn / 32, 4), dim3(32, 8)>>>(Wq, Wk, Wv, Wo);

    qkv_h_kernel<<<dim3(Cn / 128, (Bn * Tn) / 128, 3), 256, GEMM_SMEM>>>();

    flash_h_kernel<<<dim3(Tn / 64, Hn, Bn), 128>>>();

    oproj_h_kernel<<<dim3(Cn / 128, (Bn * Tn) / 128), 256, GEMM_SMEM>>>(bo, out);
}